// round 1
// baseline (speedup 1.0000x reference)
#include <cuda_runtime.h>
#include <cstdint>

// Problem dims (fixed by dataset)
#define M_TOK   512
#define N_DIM   2048
#define D_HEAD  128
#define H_HEADS 16
#define L_CACHE 4096
#define N3      6144   // 3*N_DIM

// -------- device scratch (no allocations allowed) --------
__device__ float g_q[H_HEADS * M_TOK * D_HEAD];   // [H][M][D]
__device__ float g_k[H_HEADS * M_TOK * D_HEAD];
__device__ float g_v[H_HEADS * M_TOK * D_HEAD];
__device__ float g_po[2 * H_HEADS * M_TOK * D_HEAD]; // partial numerators per L-split
__device__ float g_pd[2 * H_HEADS * M_TOK];           // partial denominators

// ============================================================
// Kernel 1: QKV GEMM  qkv = X[512,2048] @ W[2048,6144]
// BM=64, BN=128, BK=16, 128 threads, 8x8 thread tiles.
// Epilogue scatters into g_q/g_k/g_v in [H][M][D] layout.
// ============================================================
__global__ __launch_bounds__(128) void qkv_gemm_kernel(
    const float* __restrict__ X, const float* __restrict__ W)
{
    __shared__ float As[16][68];    // X tile transposed [k][m], pad 68 (272B rows, 16B aligned)
    __shared__ float Bs[16][128];   // W tile [k][n]

    const int t  = threadIdx.x;
    const int tx = t & 15;          // n-group 0..15
    const int ty = t >> 4;          // m-group 0..7
    const int m0 = blockIdx.y * 64;
    const int n0 = blockIdx.x * 128;

    float acc[8][8];
    #pragma unroll
    for (int i = 0; i < 8; ++i)
        #pragma unroll
        for (int j = 0; j < 8; ++j) acc[i][j] = 0.f;

    for (int k0 = 0; k0 < N_DIM; k0 += 16) {
        // load X tile 64x16 (transpose to As[k][m])
        #pragma unroll
        for (int it = 0; it < 2; ++it) {
            int idx = t + it * 128;          // 0..255 float4 slots
            int row = idx >> 2;              // m 0..63
            int kq  = (idx & 3) * 4;         // k 0,4,8,12
            float4 v = *(const float4*)(X + (m0 + row) * N_DIM + k0 + kq);
            As[kq + 0][row] = v.x;
            As[kq + 1][row] = v.y;
            As[kq + 2][row] = v.z;
            As[kq + 3][row] = v.w;
        }
        // load W tile 16x128
        #pragma unroll
        for (int it = 0; it < 4; ++it) {
            int idx = t + it * 128;          // 0..511 float4 slots
            int kr  = idx >> 5;              // k 0..15
            int nq  = (idx & 31) * 4;        // n 0..124
            *(float4*)(&Bs[kr][nq]) = *(const float4*)(W + (k0 + kr) * N3 + n0 + nq);
        }
        __syncthreads();

        #pragma unroll
        for (int k = 0; k < 16; ++k) {
            float ra[8], rb[8];
            *(float4*)(ra)     = *(const float4*)(&As[k][ty * 8]);
            *(float4*)(ra + 4) = *(const float4*)(&As[k][ty * 8 + 4]);
            *(float4*)(rb)     = *(const float4*)(&Bs[k][tx * 8]);
            *(float4*)(rb + 4) = *(const float4*)(&Bs[k][tx * 8 + 4]);
            #pragma unroll
            for (int i = 0; i < 8; ++i)
                #pragma unroll
                for (int j = 0; j < 8; ++j)
                    acc[i][j] = fmaf(ra[i], rb[j], acc[i][j]);
        }
        __syncthreads();
    }

    // Epilogue: block column == one (part, head). part = q/k/v.
    const int part = blockIdx.x >> 4;
    const int h    = blockIdx.x & 15;
    float* dst = (part == 0 ? g_q : (part == 1 ? g_k : g_v)) + h * (M_TOK * D_HEAD);

    #pragma unroll
    for (int i = 0; i < 8; ++i) {
        int m = m0 + ty * 8 + i;
        float4 v0 = make_float4(acc[i][0], acc[i][1], acc[i][2], acc[i][3]);
        float4 v1 = make_float4(acc[i][4], acc[i][5], acc[i][6], acc[i][7]);
        *(float4*)(dst + m * D_HEAD + tx * 8)     = v0;
        *(float4*)(dst + m * D_HEAD + tx * 8 + 4) = v1;
    }
}

// ============================================================
// Kernel 2: RMS norm rows of g_q and g_k (warp per row)
// ============================================================
__global__ __launch_bounds__(256) void rmsnorm_kernel()
{
    const int warp = threadIdx.x >> 5;
    const int lane = threadIdx.x & 31;
    const int row  = blockIdx.x * 8 + warp;         // 0 .. H*M-1
    float* base = (blockIdx.y == 0 ? g_q : g_k) + row * D_HEAD;

    float4 v = *(float4*)(base + lane * 4);
    float ss = v.x * v.x + v.y * v.y + v.z * v.z + v.w * v.w;
    #pragma unroll
    for (int off = 16; off > 0; off >>= 1)
        ss += __shfl_xor_sync(0xffffffffu, ss, off);
    float s = rsqrtf(ss * (1.0f / 128.0f));
    v.x *= s; v.y *= s; v.z *= s; v.w *= s;
    *(float4*)(base + lane * 4) = v;
}

// ============================================================
// Kernel 3: flash-style attention (plain exp, no max shift — matches ref)
// grid (M/128, H, 2 L-splits), 256 threads, Bq=128, BL=128, 8x8 tiles.
// smem: Qs[k][m] 64KB, KVs 64KB (K transposed then V natural), Ps[m][l] pitch 130.
// ============================================================
#define ATTN_SMEM_FLOATS (128*128 + 128*128 + 128*130)

__global__ __launch_bounds__(256, 1) void attn_kernel(
    const float* __restrict__ cK, const float* __restrict__ cV,
    const int* __restrict__ Pp)
{
    extern __shared__ float sm[];
    float* Qs  = sm;                 // [128][128] k-major: Qs[d][m]
    float* KVs = sm + 128 * 128;     // K: [d][l], later V: [l][d]
    float* Ps  = sm + 2 * 128 * 128; // [m][l] pitch 130

    const int P  = Pp[0];
    const int t  = threadIdx.x;
    const int tx = t & 15;           // 16 col-groups
    const int ty = t >> 4;           // 16 row-groups
    const int h  = blockIdx.y;
    const int m0 = blockIdx.x * 128;
    const int z  = blockIdx.z;

    // load Q tile transposed: Qs[d][m]
    const float* qbase = g_q + (h * M_TOK + m0) * D_HEAD;
    #pragma unroll
    for (int it = 0; it < 16; ++it) {
        int idx = t + it * 256;      // 0..4095 float4 slots
        int row = idx & 127;         // m (consecutive lanes -> consecutive m: STS conflict-free)
        int dq  = (idx >> 7) * 4;    // d 0..124
        float4 v = *(const float4*)(qbase + row * D_HEAD + dq);
        Qs[(dq + 0) * 128 + row] = v.x;
        Qs[(dq + 1) * 128 + row] = v.y;
        Qs[(dq + 2) * 128 + row] = v.z;
        Qs[(dq + 3) * 128 + row] = v.w;
    }

    float out_acc[8][8];
    #pragma unroll
    for (int i = 0; i < 8; ++i)
        #pragma unroll
        for (int j = 0; j < 8; ++j) out_acc[i][j] = 0.f;
    float den = 0.f;

    for (int ch = 0; ch < 16; ++ch) {
        const int l0 = z * 2048 + ch * 128;
        __syncthreads();             // KVs free to overwrite; Q visible

        // load K chunk transposed: KVs[d][l]
        #pragma unroll
        for (int it = 0; it < 16; ++it) {
            int idx = t + it * 256;
            int lr  = idx & 127;
            int dq  = (idx >> 7) * 4;
            int lg  = l0 + lr;
            const float* src = (lg >= P && lg < P + M_TOK)
                ? (g_k + (h * M_TOK + (lg - P)) * D_HEAD)
                : (cK + (h * L_CACHE + lg) * D_HEAD);
            float4 v = *(const float4*)(src + dq);
            KVs[(dq + 0) * 128 + lr] = v.x;
            KVs[(dq + 1) * 128 + lr] = v.y;
            KVs[(dq + 2) * 128 + lr] = v.z;
            KVs[(dq + 3) * 128 + lr] = v.w;
        }
        __syncthreads();

        // S = Q @ K^T  (8x8 per thread over S[128][128])
        float acc[8][8];
        #pragma unroll
        for (int i = 0; i < 8; ++i)
            #pragma unroll
            for (int j = 0; j < 8; ++j) acc[i][j] = 0.f;

        #pragma unroll 4
        for (int k = 0; k < 128; ++k) {
            float rq[8], rk[8];
            *(float4*)(rq)     = *(const float4*)(Qs + k * 128 + ty * 8);
            *(float4*)(rq + 4) = *(const float4*)(Qs + k * 128 + ty * 8 + 4);
            *(float4*)(rk)     = *(const float4*)(KVs + k * 128 + tx * 8);
            *(float4*)(rk + 4) = *(const float4*)(KVs + k * 128 + tx * 8 + 4);
            #pragma unroll
            for (int i = 0; i < 8; ++i)
                #pragma unroll
                for (int j = 0; j < 8; ++j)
                    acc[i][j] = fmaf(rq[i], rk[j], acc[i][j]);
        }

        // exp -> Ps[m][l] (pitch 130), float2 stores
        #pragma unroll
        for (int i = 0; i < 8; ++i) {
            int m = ty * 8 + i;
            #pragma unroll
            for (int j = 0; j < 8; j += 2) {
                float2 e;
                e.x = __expf(acc[i][j]);
                e.y = __expf(acc[i][j + 1]);
                *(float2*)(Ps + m * 130 + tx * 8 + j) = e;
            }
        }
        __syncthreads();

        // load V chunk natural: KVs[l][d]  (overwrites K; S phase done)
        #pragma unroll
        for (int it = 0; it < 16; ++it) {
            int idx = t + it * 256;
            int lr  = idx >> 5;          // l 0..127
            int dq  = (idx & 31) * 4;    // d 0..124  (coalesced)
            int lg  = l0 + lr;
            const float* src = (lg >= P && lg < P + M_TOK)
                ? (g_v + (h * M_TOK + (lg - P)) * D_HEAD)
                : (cV + (h * L_CACHE + lg) * D_HEAD);
            *(float4*)(KVs + lr * 128 + dq) = *(const float4*)(src + dq);
        }

        // denominator: thread t<128 owns row m=t, sums its Ps row
        if (t < 128) {
            float s = 0.f;
            #pragma unroll 16
            for (int l = 0; l < 128; ++l) s += Ps[t * 130 + l];
            den += s;
        }
        __syncthreads();

        // out += P @ V
        #pragma unroll 4
        for (int l = 0; l < 128; ++l) {
            float rp[8], rv[8];
            #pragma unroll
            for (int i = 0; i < 8; ++i) rp[i] = Ps[(ty * 8 + i) * 130 + l];
            *(float4*)(rv)     = *(const float4*)(KVs + l * 128 + tx * 8);
            *(float4*)(rv + 4) = *(const float4*)(KVs + l * 128 + tx * 8 + 4);
            #pragma unroll
            for (int i = 0; i < 8; ++i)
                #pragma unroll
                for (int j = 0; j < 8; ++j)
                    out_acc[i][j] = fmaf(rp[i], rv[j], out_acc[i][j]);
        }
    }

    // write partial numerator / denominator
    float* po = g_po + ((size_t)(z * H_HEADS + h) * M_TOK + m0) * D_HEAD;
    #pragma unroll
    for (int i = 0; i < 8; ++i) {
        int m = ty * 8 + i;
        float4 v0 = make_float4(out_acc[i][0], out_acc[i][1], out_acc[i][2], out_acc[i][3]);
        float4 v1 = make_float4(out_acc[i][4], out_acc[i][5], out_acc[i][6], out_acc[i][7]);
        *(float4*)(po + m * D_HEAD + tx * 8)     = v0;
        *(float4*)(po + m * D_HEAD + tx * 8 + 4) = v1;
    }
    if (t < 128)
        g_pd[(z * H_HEADS + h) * M_TOK + m0 + t] = den;
}

// ============================================================
// Kernel 4: combine L-splits and write output [M, H*D]
// ============================================================
__global__ __launch_bounds__(256) void combine_kernel(float* __restrict__ out)
{
    int idx = blockIdx.x * 256 + threadIdx.x;     // float4 index over H*M*D
    int e = idx * 4;                              // element index in [H][M][D]
    int d = e & 127;
    int m = (e >> 7) & 511;
    int h = e >> 16;

    float4 a = *(const float4*)(g_po + e);
    float4 b = *(const float4*)(g_po + H_HEADS * M_TOK * D_HEAD + e);
    float dn = g_pd[h * M_TOK + m] + g_pd[H_HEADS * M_TOK + h * M_TOK + m];
    float inv = 1.0f / dn;
    float4 r = make_float4((a.x + b.x) * inv, (a.y + b.y) * inv,
                           (a.z + b.z) * inv, (a.w + b.w) * inv);
    *(float4*)(out + m * N_DIM + h * D_HEAD + d) = r;
}

// ============================================================
extern "C" void kernel_launch(void* const* d_in, const int* in_sizes, int n_in,
                              void* d_out, int out_size)
{
    const float* X  = (const float*)d_in[0];
    const float* W  = (const float*)d_in[1];
    const float* cK = (const float*)d_in[2];
    const float* cV = (const float*)d_in[3];
    const int*   Pp = (const int*)d_in[4];
    float* out = (float*)d_out;

    const int attn_smem = ATTN_SMEM_FLOATS * sizeof(float); // ~193 KB
    cudaFuncSetAttribute(attn_kernel,
                         cudaFuncAttributeMaxDynamicSharedMemorySize, attn_smem);

    qkv_gemm_kernel<<<dim3(N3 / 128, M_TOK / 64), 128>>>(X, W);
    rmsnorm_kernel<<<dim3((H_HEADS * M_TOK) / 8, 2), 256>>>();
    attn_kernel<<<dim3(M_TOK / 128, H_HEADS, 2), 256, attn_smem>>>(cK, cV, Pp);
    combine_kernel<<<(H_HEADS * M_TOK * D_HEAD / 4) / 256, 256>>>(out);
}

// round 2
// speedup vs baseline: 1.6212x; 1.6212x over previous
#include <cuda_runtime.h>
#include <cstdint>

// Problem dims (fixed by dataset)
#define M_TOK   512
#define N_DIM   2048
#define D_HEAD  128
#define H_HEADS 16
#define L_CACHE 4096
#define N3      6144   // 3*N_DIM

// -------- device scratch (no allocations allowed) --------
__device__ float g_q[H_HEADS * M_TOK * D_HEAD];   // [H][M][D]
__device__ float g_k[H_HEADS * M_TOK * D_HEAD];
__device__ float g_v[H_HEADS * M_TOK * D_HEAD];
__device__ float g_po[2 * H_HEADS * M_TOK * D_HEAD]; // partial numerators per L-split
__device__ float g_pd[2 * H_HEADS * M_TOK];           // partial denominators

// ============================================================
// Kernel 1: QKV GEMM  qkv = X[512,2048] @ W[2048,6144]
// BM=64, BN=128, BK=16, 128 threads, 8x8 thread tiles.
// Epilogue scatters into g_q/g_k/g_v in [H][M][D] layout.
// ============================================================
__global__ __launch_bounds__(128) void qkv_gemm_kernel(
    const float* __restrict__ X, const float* __restrict__ W)
{
    __shared__ float As[16][68];    // X tile transposed [k][m], pad 68 (272B rows, 16B aligned)
    __shared__ float Bs[16][128];   // W tile [k][n]

    const int t  = threadIdx.x;
    const int tx = t & 15;          // n-group 0..15
    const int ty = t >> 4;          // m-group 0..7
    const int m0 = blockIdx.y * 64;
    const int n0 = blockIdx.x * 128;

    float acc[8][8];
    #pragma unroll
    for (int i = 0; i < 8; ++i)
        #pragma unroll
        for (int j = 0; j < 8; ++j) acc[i][j] = 0.f;

    for (int k0 = 0; k0 < N_DIM; k0 += 16) {
        // load X tile 64x16 (transpose to As[k][m])
        #pragma unroll
        for (int it = 0; it < 2; ++it) {
            int idx = t + it * 128;          // 0..255 float4 slots
            int row = idx >> 2;              // m 0..63
            int kq  = (idx & 3) * 4;         // k 0,4,8,12
            float4 v = *(const float4*)(X + (m0 + row) * N_DIM + k0 + kq);
            As[kq + 0][row] = v.x;
            As[kq + 1][row] = v.y;
            As[kq + 2][row] = v.z;
            As[kq + 3][row] = v.w;
        }
        // load W tile 16x128
        #pragma unroll
        for (int it = 0; it < 4; ++it) {
            int idx = t + it * 128;          // 0..511 float4 slots
            int kr  = idx >> 5;              // k 0..15
            int nq  = (idx & 31) * 4;        // n 0..124
            *(float4*)(&Bs[kr][nq]) = *(const float4*)(W + (k0 + kr) * N3 + n0 + nq);
        }
        __syncthreads();

        #pragma unroll
        for (int k = 0; k < 16; ++k) {
            float ra[8], rb[8];
            *(float4*)(ra)     = *(const float4*)(&As[k][ty * 8]);
            *(float4*)(ra + 4) = *(const float4*)(&As[k][ty * 8 + 4]);
            *(float4*)(rb)     = *(const float4*)(&Bs[k][tx * 8]);
            *(float4*)(rb + 4) = *(const float4*)(&Bs[k][tx * 8 + 4]);
            #pragma unroll
            for (int i = 0; i < 8; ++i)
                #pragma unroll
                for (int j = 0; j < 8; ++j)
                    acc[i][j] = fmaf(ra[i], rb[j], acc[i][j]);
        }
        __syncthreads();
    }

    // Epilogue: block column == one (part, head). part = q/k/v.
    const int part = blockIdx.x >> 4;
    const int h    = blockIdx.x & 15;
    float* dst = (part == 0 ? g_q : (part == 1 ? g_k : g_v)) + h * (M_TOK * D_HEAD);

    #pragma unroll
    for (int i = 0; i < 8; ++i) {
        int m = m0 + ty * 8 + i;
        float4 v0 = make_float4(acc[i][0], acc[i][1], acc[i][2], acc[i][3]);
        float4 v1 = make_float4(acc[i][4], acc[i][5], acc[i][6], acc[i][7]);
        *(float4*)(dst + m * D_HEAD + tx * 8)     = v0;
        *(float4*)(dst + m * D_HEAD + tx * 8 + 4) = v1;
    }
}

// ============================================================
// Kernel 2: RMS norm rows of g_q and g_k (warp per row)
// ============================================================
__global__ __launch_bounds__(256) void rmsnorm_kernel()
{
    const int warp = threadIdx.x >> 5;
    const int lane = threadIdx.x & 31;
    const int row  = blockIdx.x * 8 + warp;         // 0 .. H*M-1
    float* base = (blockIdx.y == 0 ? g_q : g_k) + row * D_HEAD;

    float4 v = *(float4*)(base + lane * 4);
    float ss = v.x * v.x + v.y * v.y + v.z * v.z + v.w * v.w;
    #pragma unroll
    for (int off = 16; off > 0; off >>= 1)
        ss += __shfl_xor_sync(0xffffffffu, ss, off);
    float s = rsqrtf(ss * (1.0f / 128.0f));
    v.x *= s; v.y *= s; v.z *= s; v.w *= s;
    *(float4*)(base + lane * 4) = v;
}

// ============================================================
// Kernel 3: flash-style attention (plain exp, no max shift — matches ref)
// grid (M/128, H, 2 L-splits), 256 threads, Bq=128, BL=128, 8x8 tiles.
// smem: Qs[k][m] 64KB, KVs 64KB (K transposed then V natural), Ps[m][l] pitch 130.
// ============================================================
#define ATTN_SMEM_FLOATS (128*128 + 128*128 + 128*130)

__global__ __launch_bounds__(256, 1) void attn_kernel(
    const float* __restrict__ cK, const float* __restrict__ cV,
    const int* __restrict__ Pp)
{
    extern __shared__ float sm[];
    float* Qs  = sm;                 // [128][128] k-major: Qs[d][m]
    float* KVs = sm + 128 * 128;     // K: [d][l], later V: [l][d]
    float* Ps  = sm + 2 * 128 * 128; // [m][l] pitch 130

    const int P  = Pp[0];
    const int t  = threadIdx.x;
    const int tx = t & 15;           // 16 col-groups
    const int ty = t >> 4;           // 16 row-groups
    const int h  = blockIdx.y;
    const int m0 = blockIdx.x * 128;
    const int z  = blockIdx.z;

    // load Q tile transposed: Qs[d][m]
    const float* qbase = g_q + (h * M_TOK + m0) * D_HEAD;
    #pragma unroll
    for (int it = 0; it < 16; ++it) {
        int idx = t + it * 256;      // 0..4095 float4 slots
        int row = idx & 127;         // m (consecutive lanes -> consecutive m: STS conflict-free)
        int dq  = (idx >> 7) * 4;    // d 0..124
        float4 v = *(const float4*)(qbase + row * D_HEAD + dq);
        Qs[(dq + 0) * 128 + row] = v.x;
        Qs[(dq + 1) * 128 + row] = v.y;
        Qs[(dq + 2) * 128 + row] = v.z;
        Qs[(dq + 3) * 128 + row] = v.w;
    }

    float out_acc[8][8];
    #pragma unroll
    for (int i = 0; i < 8; ++i)
        #pragma unroll
        for (int j = 0; j < 8; ++j) out_acc[i][j] = 0.f;
    float den = 0.f;

    for (int ch = 0; ch < 16; ++ch) {
        const int l0 = z * 2048 + ch * 128;
        __syncthreads();             // KVs free to overwrite; Q visible

        // load K chunk transposed: KVs[d][l]
        #pragma unroll
        for (int it = 0; it < 16; ++it) {
            int idx = t + it * 256;
            int lr  = idx & 127;
            int dq  = (idx >> 7) * 4;
            int lg  = l0 + lr;
            const float* src = (lg >= P && lg < P + M_TOK)
                ? (g_k + (h * M_TOK + (lg - P)) * D_HEAD)
                : (cK + (h * L_CACHE + lg) * D_HEAD);
            float4 v = *(const float4*)(src + dq);
            KVs[(dq + 0) * 128 + lr] = v.x;
            KVs[(dq + 1) * 128 + lr] = v.y;
            KVs[(dq + 2) * 128 + lr] = v.z;
            KVs[(dq + 3) * 128 + lr] = v.w;
        }
        __syncthreads();

        // S = Q @ K^T  (8x8 per thread over S[128][128])
        float acc[8][8];
        #pragma unroll
        for (int i = 0; i < 8; ++i)
            #pragma unroll
            for (int j = 0; j < 8; ++j) acc[i][j] = 0.f;

        #pragma unroll 4
        for (int k = 0; k < 128; ++k) {
            float rq[8], rk[8];
            *(float4*)(rq)     = *(const float4*)(Qs + k * 128 + ty * 8);
            *(float4*)(rq + 4) = *(const float4*)(Qs + k * 128 + ty * 8 + 4);
            *(float4*)(rk)     = *(const float4*)(KVs + k * 128 + tx * 8);
            *(float4*)(rk + 4) = *(const float4*)(KVs + k * 128 + tx * 8 + 4);
            #pragma unroll
            for (int i = 0; i < 8; ++i)
                #pragma unroll
                for (int j = 0; j < 8; ++j)
                    acc[i][j] = fmaf(rq[i], rk[j], acc[i][j]);
        }

        // exp -> Ps[m][l] (pitch 130), float2 stores
        #pragma unroll
        for (int i = 0; i < 8; ++i) {
            int m = ty * 8 + i;
            #pragma unroll
            for (int j = 0; j < 8; j += 2) {
                float2 e;
                e.x = __expf(acc[i][j]);
                e.y = __expf(acc[i][j + 1]);
                *(float2*)(Ps + m * 130 + tx * 8 + j) = e;
            }
        }
        __syncthreads();

        // load V chunk natural: KVs[l][d]  (overwrites K; S phase done)
        #pragma unroll
        for (int it = 0; it < 16; ++it) {
            int idx = t + it * 256;
            int lr  = idx >> 5;          // l 0..127
            int dq  = (idx & 31) * 4;    // d 0..124  (coalesced)
            int lg  = l0 + lr;
            const float* src = (lg >= P && lg < P + M_TOK)
                ? (g_v + (h * M_TOK + (lg - P)) * D_HEAD)
                : (cV + (h * L_CACHE + lg) * D_HEAD);
            *(float4*)(KVs + lr * 128 + dq) = *(const float4*)(src + dq);
        }

        // denominator: thread t<128 owns row m=t, sums its Ps row
        if (t < 128) {
            float s = 0.f;
            #pragma unroll 16
            for (int l = 0; l < 128; ++l) s += Ps[t * 130 + l];
            den += s;
        }
        __syncthreads();

        // out += P @ V
        #pragma unroll 4
        for (int l = 0; l < 128; ++l) {
            float rp[8], rv[8];
            #pragma unroll
            for (int i = 0; i < 8; ++i) rp[i] = Ps[(ty * 8 + i) * 130 + l];
            *(float4*)(rv)     = *(const float4*)(KVs + l * 128 + tx * 8);
            *(float4*)(rv + 4) = *(const float4*)(KVs + l * 128 + tx * 8 + 4);
            #pragma unroll
            for (int i = 0; i < 8; ++i)
                #pragma unroll
                for (int j = 0; j < 8; ++j)
                    out_acc[i][j] = fmaf(rp[i], rv[j], out_acc[i][j]);
        }
    }

    // write partial numerator / denominator
    float* po = g_po + ((size_t)(z * H_HEADS + h) * M_TOK + m0) * D_HEAD;
    #pragma unroll
    for (int i = 0; i < 8; ++i) {
        int m = ty * 8 + i;
        float4 v0 = make_float4(out_acc[i][0], out_acc[i][1], out_acc[i][2], out_acc[i][3]);
        float4 v1 = make_float4(out_acc[i][4], out_acc[i][5], out_acc[i][6], out_acc[i][7]);
        *(float4*)(po + m * D_HEAD + tx * 8)     = v0;
        *(float4*)(po + m * D_HEAD + tx * 8 + 4) = v1;
    }
    if (t < 128)
        g_pd[(z * H_HEADS + h) * M_TOK + m0 + t] = den;
}

// ============================================================
// Kernel 4: combine L-splits and write output [M, H*D]
// ============================================================
__global__ __launch_bounds__(256) void combine_kernel(float* __restrict__ out)
{
    int idx = blockIdx.x * 256 + threadIdx.x;     // float4 index over H*M*D
    int e = idx * 4;                              // element index in [H][M][D]
    int d = e & 127;
    int m = (e >> 7) & 511;
    int h = e >> 16;

    float4 a = *(const float4*)(g_po + e);
    float4 b = *(const float4*)(g_po + H_HEADS * M_TOK * D_HEAD + e);
    float dn = g_pd[h * M_TOK + m] + g_pd[H_HEADS * M_TOK + h * M_TOK + m];
    float inv = 1.0f / dn;
    float4 r = make_float4((a.x + b.x) * inv, (a.y + b.y) * inv,
                           (a.z + b.z) * inv, (a.w + b.w) * inv);
    *(float4*)(out + m * N_DIM + h * D_HEAD + d) = r;
}

// ============================================================
extern "C" void kernel_launch(void* const* d_in, const int* in_sizes, int n_in,
                              void* d_out, int out_size)
{
    const float* X  = (const float*)d_in[0];
    const float* W  = (const float*)d_in[1];
    const float* cK = (const float*)d_in[2];
    const float* cV = (const float*)d_in[3];
    const int*   Pp = (const int*)d_in[4];
    float* out = (float*)d_out;

    const int attn_smem = ATTN_SMEM_FLOATS * sizeof(float); // ~193 KB
    cudaFuncSetAttribute(attn_kernel,
                         cudaFuncAttributeMaxDynamicSharedMemorySize, attn_smem);

    qkv_gemm_kernel<<<dim3(N3 / 128, M_TOK / 64), 128>>>(X, W);
    rmsnorm_kernel<<<dim3((H_HEADS * M_TOK) / 8, 2), 256>>>();
    attn_kernel<<<dim3(M_TOK / 128, H_HEADS, 2), 256, attn_smem>>>(cK, cV, Pp);
    combine_kernel<<<(H_HEADS * M_TOK * D_HEAD / 4) / 256, 256>>>(out);
}

// round 3
// speedup vs baseline: 1.6255x; 1.0027x over previous
#include <cuda_runtime.h>
#include <cstdint>

// Problem dims (fixed by dataset)
#define M_TOK   512
#define N_DIM   2048
#define D_HEAD  128
#define H_HEADS 16
#define L_CACHE 4096
#define N3      6144   // 3*N_DIM

// -------- device scratch (no allocations allowed) --------
__device__ float g_q[H_HEADS * M_TOK * D_HEAD];   // [H][M][D]
__device__ float g_k[H_HEADS * M_TOK * D_HEAD];
__device__ float g_v[H_HEADS * M_TOK * D_HEAD];
__device__ float g_po[2 * H_HEADS * M_TOK * D_HEAD]; // partial numerators per L-split
__device__ float g_pd[2 * H_HEADS * M_TOK];           // partial denominators

// ============================================================
// Kernel 1: QKV GEMM  qkv = X[512,2048] @ W[2048,6144]
// BM=64, BN=128, BK=16, 128 threads, 8x8 thread tiles.
// Epilogue scatters into g_q/g_k/g_v in [H][M][D] layout.
// ============================================================
__global__ __launch_bounds__(128) void qkv_gemm_kernel(
    const float* __restrict__ X, const float* __restrict__ W)
{
    __shared__ float As[16][68];    // X tile transposed [k][m], pad 68 (272B rows, 16B aligned)
    __shared__ float Bs[16][128];   // W tile [k][n]

    const int t  = threadIdx.x;
    const int tx = t & 15;          // n-group 0..15
    const int ty = t >> 4;          // m-group 0..7
    const int m0 = blockIdx.y * 64;
    const int n0 = blockIdx.x * 128;

    float acc[8][8];
    #pragma unroll
    for (int i = 0; i < 8; ++i)
        #pragma unroll
        for (int j = 0; j < 8; ++j) acc[i][j] = 0.f;

    for (int k0 = 0; k0 < N_DIM; k0 += 16) {
        // load X tile 64x16 (transpose to As[k][m])
        #pragma unroll
        for (int it = 0; it < 2; ++it) {
            int idx = t + it * 128;          // 0..255 float4 slots
            int row = idx >> 2;              // m 0..63
            int kq  = (idx & 3) * 4;         // k 0,4,8,12
            float4 v = *(const float4*)(X + (m0 + row) * N_DIM + k0 + kq);
            As[kq + 0][row] = v.x;
            As[kq + 1][row] = v.y;
            As[kq + 2][row] = v.z;
            As[kq + 3][row] = v.w;
        }
        // load W tile 16x128
        #pragma unroll
        for (int it = 0; it < 4; ++it) {
            int idx = t + it * 128;          // 0..511 float4 slots
            int kr  = idx >> 5;              // k 0..15
            int nq  = (idx & 31) * 4;        // n 0..124
            *(float4*)(&Bs[kr][nq]) = *(const float4*)(W + (k0 + kr) * N3 + n0 + nq);
        }
        __syncthreads();

        #pragma unroll
        for (int k = 0; k < 16; ++k) {
            float ra[8], rb[8];
            *(float4*)(ra)     = *(const float4*)(&As[k][ty * 8]);
            *(float4*)(ra + 4) = *(const float4*)(&As[k][ty * 8 + 4]);
            *(float4*)(rb)     = *(const float4*)(&Bs[k][tx * 8]);
            *(float4*)(rb + 4) = *(const float4*)(&Bs[k][tx * 8 + 4]);
            #pragma unroll
            for (int i = 0; i < 8; ++i)
                #pragma unroll
                for (int j = 0; j < 8; ++j)
                    acc[i][j] = fmaf(ra[i], rb[j], acc[i][j]);
        }
        __syncthreads();
    }

    // Epilogue: block column == one (part, head). part = q/k/v.
    const int part = blockIdx.x >> 4;
    const int h    = blockIdx.x & 15;
    float* dst = (part == 0 ? g_q : (part == 1 ? g_k : g_v)) + h * (M_TOK * D_HEAD);

    #pragma unroll
    for (int i = 0; i < 8; ++i) {
        int m = m0 + ty * 8 + i;
        float4 v0 = make_float4(acc[i][0], acc[i][1], acc[i][2], acc[i][3]);
        float4 v1 = make_float4(acc[i][4], acc[i][5], acc[i][6], acc[i][7]);
        *(float4*)(dst + m * D_HEAD + tx * 8)     = v0;
        *(float4*)(dst + m * D_HEAD + tx * 8 + 4) = v1;
    }
}

// ============================================================
// Kernel 2: RMS norm rows of g_q and g_k (warp per row)
// ============================================================
__global__ __launch_bounds__(256) void rmsnorm_kernel()
{
    const int warp = threadIdx.x >> 5;
    const int lane = threadIdx.x & 31;
    const int row  = blockIdx.x * 8 + warp;         // 0 .. H*M-1
    float* base = (blockIdx.y == 0 ? g_q : g_k) + row * D_HEAD;

    float4 v = *(float4*)(base + lane * 4);
    float ss = v.x * v.x + v.y * v.y + v.z * v.z + v.w * v.w;
    #pragma unroll
    for (int off = 16; off > 0; off >>= 1)
        ss += __shfl_xor_sync(0xffffffffu, ss, off);
    float s = rsqrtf(ss * (1.0f / 128.0f));
    v.x *= s; v.y *= s; v.z *= s; v.w *= s;
    *(float4*)(base + lane * 4) = v;
}

// ============================================================
// Kernel 3: flash-style attention (plain exp, no max shift — matches ref)
// grid (M/128, H, 2 L-splits), 256 threads, Bq=128, BL=128, 8x8 tiles.
// smem: Qs[k][m] 64KB, KVs 64KB (K transposed then V natural), Ps[m][l] pitch 130.
// ============================================================
#define ATTN_SMEM_FLOATS (128*128 + 128*128 + 128*130)

__global__ __launch_bounds__(256, 1) void attn_kernel(
    const float* __restrict__ cK, const float* __restrict__ cV,
    const int* __restrict__ Pp)
{
    extern __shared__ float sm[];
    float* Qs  = sm;                 // [128][128] k-major: Qs[d][m]
    float* KVs = sm + 128 * 128;     // K: [d][l], later V: [l][d]
    float* Ps  = sm + 2 * 128 * 128; // [m][l] pitch 130

    const int P  = Pp[0];
    const int t  = threadIdx.x;
    const int tx = t & 15;           // 16 col-groups
    const int ty = t >> 4;           // 16 row-groups
    const int h  = blockIdx.y;
    const int m0 = blockIdx.x * 128;
    const int z  = blockIdx.z;

    // load Q tile transposed: Qs[d][m]
    const float* qbase = g_q + (h * M_TOK + m0) * D_HEAD;
    #pragma unroll
    for (int it = 0; it < 16; ++it) {
        int idx = t + it * 256;      // 0..4095 float4 slots
        int row = idx & 127;         // m (consecutive lanes -> consecutive m: STS conflict-free)
        int dq  = (idx >> 7) * 4;    // d 0..124
        float4 v = *(const float4*)(qbase + row * D_HEAD + dq);
        Qs[(dq + 0) * 128 + row] = v.x;
        Qs[(dq + 1) * 128 + row] = v.y;
        Qs[(dq + 2) * 128 + row] = v.z;
        Qs[(dq + 3) * 128 + row] = v.w;
    }

    float out_acc[8][8];
    #pragma unroll
    for (int i = 0; i < 8; ++i)
        #pragma unroll
        for (int j = 0; j < 8; ++j) out_acc[i][j] = 0.f;
    float den = 0.f;

    for (int ch = 0; ch < 16; ++ch) {
        const int l0 = z * 2048 + ch * 128;
        __syncthreads();             // KVs free to overwrite; Q visible

        // load K chunk transposed: KVs[d][l]
        #pragma unroll
        for (int it = 0; it < 16; ++it) {
            int idx = t + it * 256;
            int lr  = idx & 127;
            int dq  = (idx >> 7) * 4;
            int lg  = l0 + lr;
            const float* src = (lg >= P && lg < P + M_TOK)
                ? (g_k + (h * M_TOK + (lg - P)) * D_HEAD)
                : (cK + (h * L_CACHE + lg) * D_HEAD);
            float4 v = *(const float4*)(src + dq);
            KVs[(dq + 0) * 128 + lr] = v.x;
            KVs[(dq + 1) * 128 + lr] = v.y;
            KVs[(dq + 2) * 128 + lr] = v.z;
            KVs[(dq + 3) * 128 + lr] = v.w;
        }
        __syncthreads();

        // S = Q @ K^T  (8x8 per thread over S[128][128])
        float acc[8][8];
        #pragma unroll
        for (int i = 0; i < 8; ++i)
            #pragma unroll
            for (int j = 0; j < 8; ++j) acc[i][j] = 0.f;

        #pragma unroll 4
        for (int k = 0; k < 128; ++k) {
            float rq[8], rk[8];
            *(float4*)(rq)     = *(const float4*)(Qs + k * 128 + ty * 8);
            *(float4*)(rq + 4) = *(const float4*)(Qs + k * 128 + ty * 8 + 4);
            *(float4*)(rk)     = *(const float4*)(KVs + k * 128 + tx * 8);
            *(float4*)(rk + 4) = *(const float4*)(KVs + k * 128 + tx * 8 + 4);
            #pragma unroll
            for (int i = 0; i < 8; ++i)
                #pragma unroll
                for (int j = 0; j < 8; ++j)
                    acc[i][j] = fmaf(rq[i], rk[j], acc[i][j]);
        }

        // exp -> Ps[m][l] (pitch 130), float2 stores
        #pragma unroll
        for (int i = 0; i < 8; ++i) {
            int m = ty * 8 + i;
            #pragma unroll
            for (int j = 0; j < 8; j += 2) {
                float2 e;
                e.x = __expf(acc[i][j]);
                e.y = __expf(acc[i][j + 1]);
                *(float2*)(Ps + m * 130 + tx * 8 + j) = e;
            }
        }
        __syncthreads();

        // load V chunk natural: KVs[l][d]  (overwrites K; S phase done)
        #pragma unroll
        for (int it = 0; it < 16; ++it) {
            int idx = t + it * 256;
            int lr  = idx >> 5;          // l 0..127
            int dq  = (idx & 31) * 4;    // d 0..124  (coalesced)
            int lg  = l0 + lr;
            const float* src = (lg >= P && lg < P + M_TOK)
                ? (g_v + (h * M_TOK + (lg - P)) * D_HEAD)
                : (cV + (h * L_CACHE + lg) * D_HEAD);
            *(float4*)(KVs + lr * 128 + dq) = *(const float4*)(src + dq);
        }

        // denominator: thread t<128 owns row m=t, sums its Ps row
        if (t < 128) {
            float s = 0.f;
            #pragma unroll 16
            for (int l = 0; l < 128; ++l) s += Ps[t * 130 + l];
            den += s;
        }
        __syncthreads();

        // out += P @ V
        #pragma unroll 4
        for (int l = 0; l < 128; ++l) {
            float rp[8], rv[8];
            #pragma unroll
            for (int i = 0; i < 8; ++i) rp[i] = Ps[(ty * 8 + i) * 130 + l];
            *(float4*)(rv)     = *(const float4*)(KVs + l * 128 + tx * 8);
            *(float4*)(rv + 4) = *(const float4*)(KVs + l * 128 + tx * 8 + 4);
            #pragma unroll
            for (int i = 0; i < 8; ++i)
                #pragma unroll
                for (int j = 0; j < 8; ++j)
                    out_acc[i][j] = fmaf(rp[i], rv[j], out_acc[i][j]);
        }
    }

    // write partial numerator / denominator
    float* po = g_po + ((size_t)(z * H_HEADS + h) * M_TOK + m0) * D_HEAD;
    #pragma unroll
    for (int i = 0; i < 8; ++i) {
        int m = ty * 8 + i;
        float4 v0 = make_float4(out_acc[i][0], out_acc[i][1], out_acc[i][2], out_acc[i][3]);
        float4 v1 = make_float4(out_acc[i][4], out_acc[i][5], out_acc[i][6], out_acc[i][7]);
        *(float4*)(po + m * D_HEAD + tx * 8)     = v0;
        *(float4*)(po + m * D_HEAD + tx * 8 + 4) = v1;
    }
    if (t < 128)
        g_pd[(z * H_HEADS + h) * M_TOK + m0 + t] = den;
}

// ============================================================
// Kernel 4: combine L-splits and write output [M, H*D]
// ============================================================
__global__ __launch_bounds__(256) void combine_kernel(float* __restrict__ out)
{
    int idx = blockIdx.x * 256 + threadIdx.x;     // float4 index over H*M*D
    int e = idx * 4;                              // element index in [H][M][D]
    int d = e & 127;
    int m = (e >> 7) & 511;
    int h = e >> 16;

    float4 a = *(const float4*)(g_po + e);
    float4 b = *(const float4*)(g_po + H_HEADS * M_TOK * D_HEAD + e);
    float dn = g_pd[h * M_TOK + m] + g_pd[H_HEADS * M_TOK + h * M_TOK + m];
    float inv = 1.0f / dn;
    float4 r = make_float4((a.x + b.x) * inv, (a.y + b.y) * inv,
                           (a.z + b.z) * inv, (a.w + b.w) * inv);
    *(float4*)(out + m * N_DIM + h * D_HEAD + d) = r;
}

// ============================================================
extern "C" void kernel_launch(void* const* d_in, const int* in_sizes, int n_in,
                              void* d_out, int out_size)
{
    const float* X  = (const float*)d_in[0];
    const float* W  = (const float*)d_in[1];
    const float* cK = (const float*)d_in[2];
    const float* cV = (const float*)d_in[3];
    const int*   Pp = (const int*)d_in[4];
    float* out = (float*)d_out;

    const int attn_smem = ATTN_SMEM_FLOATS * sizeof(float); // ~193 KB
    cudaFuncSetAttribute(attn_kernel,
                         cudaFuncAttributeMaxDynamicSharedMemorySize, attn_smem);

    qkv_gemm_kernel<<<dim3(N3 / 128, M_TOK / 64), 128>>>(X, W);
    rmsnorm_kernel<<<dim3((H_HEADS * M_TOK) / 8, 2), 256>>>();
    attn_kernel<<<dim3(M_TOK / 128, H_HEADS, 2), 256, attn_smem>>>(cK, cV, Pp);
    combine_kernel<<<(H_HEADS * M_TOK * D_HEAD / 4) / 256, 256>>>(out);
}

// round 6
// speedup vs baseline: 2.0068x; 1.2346x over previous
#include <cuda_runtime.h>
#include <cuda_bf16.h>
#include <cstdint>

// Problem dims (fixed by dataset)
#define M_TOK   512
#define N_DIM   2048
#define D_HEAD  128
#define H_HEADS 16
#define L_CACHE 4096
#define N3      6144   // 3*N_DIM

// -------- device scratch (no allocations allowed) --------
__device__ float g_q[H_HEADS * M_TOK * D_HEAD];   // [H][M][D]
__device__ float g_k[H_HEADS * M_TOK * D_HEAD];
__device__ float g_v[H_HEADS * M_TOK * D_HEAD];
__device__ float g_po[2 * H_HEADS * M_TOK * D_HEAD]; // partial numerators per L-split
__device__ float g_pd[2 * H_HEADS * M_TOK];           // partial denominators

// bf16x3 split operands for warp-MMA QKV GEMM
__device__ __nv_bfloat16 g_xhi[M_TOK * N_DIM];        // X  [m][k]
__device__ __nv_bfloat16 g_xlo[M_TOK * N_DIM];
__device__ __nv_bfloat16 g_wthi[(size_t)N3 * N_DIM];  // W^T [n][k]
__device__ __nv_bfloat16 g_wtlo[(size_t)N3 * N_DIM];

// ============================================================
// helpers
// ============================================================
__device__ __forceinline__ uint32_t smem_u32(const void* p) {
    uint32_t a;
    asm("{ .reg .u64 t; cvta.to.shared.u64 t, %1; cvt.u32.u64 %0, t; }"
        : "=r"(a) : "l"(p));
    return a;
}

__device__ __forceinline__ void ldm_x4(uint32_t& d0, uint32_t& d1,
                                       uint32_t& d2, uint32_t& d3, uint32_t addr) {
    asm volatile("ldmatrix.sync.aligned.m8n8.x4.shared.b16 {%0,%1,%2,%3}, [%4];"
                 : "=r"(d0), "=r"(d1), "=r"(d2), "=r"(d3) : "r"(addr));
}

__device__ __forceinline__ void mma16816(float* c, const uint32_t* a, const uint32_t* b) {
    asm volatile(
        "mma.sync.aligned.m16n8k16.row.col.f32.bf16.bf16.f32 "
        "{%0,%1,%2,%3}, {%4,%5,%6,%7}, {%8,%9}, {%0,%1,%2,%3};"
        : "+f"(c[0]), "+f"(c[1]), "+f"(c[2]), "+f"(c[3])
        : "r"(a[0]), "r"(a[1]), "r"(a[2]), "r"(a[3]), "r"(b[0]), "r"(b[1]));
}

__device__ __forceinline__ void split_bf16(float x, __nv_bfloat16& hi, __nv_bfloat16& lo) {
    hi = __float2bfloat16_rn(x);
    lo = __float2bfloat16_rn(x - __bfloat162float(hi));
}

// ============================================================
// Kernel 0a: split X -> g_xhi/g_xlo  [m][k]
// ============================================================
__global__ __launch_bounds__(256) void convert_x_kernel(const float* __restrict__ X)
{
    int idx = blockIdx.x * 256 + threadIdx.x;      // float4 index, 262144 total
    float4 v = *(const float4*)(X + idx * 4);
    __nv_bfloat16 h0, l0, h1, l1, h2, l2, h3, l3;
    split_bf16(v.x, h0, l0); split_bf16(v.y, h1, l1);
    split_bf16(v.z, h2, l2); split_bf16(v.w, h3, l3);
    __nv_bfloat162* ph = (__nv_bfloat162*)(g_xhi + idx * 4);
    __nv_bfloat162* pl = (__nv_bfloat162*)(g_xlo + idx * 4);
    ph[0] = __nv_bfloat162(h0, h1); ph[1] = __nv_bfloat162(h2, h3);
    pl[0] = __nv_bfloat162(l0, l1); pl[1] = __nv_bfloat162(l2, l3);
}

// ============================================================
// Kernel 0b: transpose+split W[k][n] -> g_wthi/g_wtlo [n][k]
// ============================================================
__global__ __launch_bounds__(256) void convert_w_kernel(const float* __restrict__ W)
{
    __shared__ float tile[32][33];
    const int n0 = blockIdx.x * 32;
    const int k0 = blockIdx.y * 32;
    const int tx = threadIdx.x, ty = threadIdx.y;

    #pragma unroll
    for (int l = 0; l < 4; ++l)
        tile[ty * 4 + l][tx] = W[(size_t)(k0 + ty * 4 + l) * N3 + n0 + tx];
    __syncthreads();

    #pragma unroll
    for (int l = 0; l < 4; ++l) {
        int nl = ty * 4 + l;
        float x = tile[tx][nl];
        __nv_bfloat16 hi, lo;
        split_bf16(x, hi, lo);
        size_t o = (size_t)(n0 + nl) * N_DIM + k0 + tx;
        g_wthi[o] = hi;
        g_wtlo[o] = lo;
    }
}

// ============================================================
// Kernel 1: QKV GEMM via mma.sync bf16x3 (hi*hi + hi*lo + lo*hi)
// BM=128, BN=64, BK=32; 256 thr = 8 warps (4x2), warp tile 32x32.
// smem tiles pitch 40 elems (80B): STS and ldmatrix conflict-free.
// ============================================================
#define PITCH_E   40
#define PITCH_B   80
#define A_TILE_B  (128 * PITCH_B)   // 10240
#define B_TILE_B  (64  * PITCH_B)   // 5120
#define OFF_AHI   0
#define OFF_ALO   A_TILE_B
#define OFF_BHI   (2 * A_TILE_B)
#define OFF_BLO   (2 * A_TILE_B + B_TILE_B)
#define BUF_B     (2 * A_TILE_B + 2 * B_TILE_B)   // 30720
#define GEMM_SMEM (2 * BUF_B)                     // 61440

__global__ __launch_bounds__(256) void qkv_mma_kernel()
{
    extern __shared__ __align__(128) char sm[];
    const uint32_t sb = smem_u32(sm);
    const int t    = threadIdx.x;
    const int lane = t & 31;
    const int wid  = t >> 5;
    const int wm   = wid & 3;        // 0..3  (m-warp)
    const int wn   = wid >> 2;       // 0..1  (n-warp)
    const int lg   = lane >> 3;      // ldmatrix group 0..3
    const int lr   = lane & 7;
    const int m0   = blockIdx.y * 128;
    const int n0   = blockIdx.x * 64;

    // ---- load one BK=32 K-slice of all 4 split tiles into buffer buf ----
    auto load_tiles = [&](int k0, int buf) {
        char* base = sm + buf * BUF_B;
        #pragma unroll
        for (int i = 0; i < 6; ++i) {
            int idx = t + i * 256;                 // 0..1535 16B chunks
            const __nv_bfloat16* gsrc;
            int local, off;
            if (idx < 512)       { gsrc = g_xhi  + (size_t)m0 * N_DIM; local = idx;        off = OFF_AHI; }
            else if (idx < 1024) { gsrc = g_xlo  + (size_t)m0 * N_DIM; local = idx - 512;  off = OFF_ALO; }
            else if (idx < 1280) { gsrc = g_wthi + (size_t)n0 * N_DIM; local = idx - 1024; off = OFF_BHI; }
            else                 { gsrc = g_wtlo + (size_t)n0 * N_DIM; local = idx - 1280; off = OFF_BLO; }
            int r = local >> 2, c = local & 3;
            uint4 v = *(const uint4*)(gsrc + (size_t)r * N_DIM + k0 + c * 8);
            *(uint4*)(base + off + r * PITCH_B + c * 16) = v;
        }
    };

    float acc[2][4][4];
    #pragma unroll
    for (int mi = 0; mi < 2; ++mi)
        #pragma unroll
        for (int nf = 0; nf < 4; ++nf)
            #pragma unroll
            for (int e = 0; e < 4; ++e) acc[mi][nf][e] = 0.f;

    load_tiles(0, 0);

    const int NIT = N_DIM / 32;    // 64
    for (int it = 0; it < NIT; ++it) {
        const int buf = it & 1;
        __syncthreads();
        if (it + 1 < NIT) load_tiles((it + 1) * 32, buf ^ 1);

        const uint32_t bb = sb + buf * BUF_B;
        #pragma unroll
        for (int ks = 0; ks < 2; ++ks) {
            uint32_t aHi[2][4], aLo[2][4], bHi[4][2], bLo[4][2];
            // A fragments: 16x16 tiles, row-major
            #pragma unroll
            for (int mi = 0; mi < 2; ++mi) {
                int row = wm * 32 + mi * 16 + lr + (lg & 1) * 8;
                int col = ks * 16 + (lg >> 1) * 8;
                uint32_t ad = bb + OFF_AHI + row * PITCH_B + col * 2;
                ldm_x4(aHi[mi][0], aHi[mi][1], aHi[mi][2], aHi[mi][3], ad);
                ldm_x4(aLo[mi][0], aLo[mi][1], aLo[mi][2], aLo[mi][3], ad + (OFF_ALO - OFF_AHI));
            }
            // B fragments: [n][k] tiles -> col-major k x n for mma
            #pragma unroll
            for (int nj = 0; nj < 2; ++nj) {
                int row = wn * 32 + nj * 16 + (lg >> 1) * 8 + lr;
                int col = ks * 16 + (lg & 1) * 8;
                uint32_t bd = bb + OFF_BHI + row * PITCH_B + col * 2;
                uint32_t d0, d1, d2, d3;
                ldm_x4(d0, d1, d2, d3, bd);
                bHi[nj * 2][0] = d0; bHi[nj * 2][1] = d1;
                bHi[nj * 2 + 1][0] = d2; bHi[nj * 2 + 1][1] = d3;
                ldm_x4(d0, d1, d2, d3, bd + (OFF_BLO - OFF_BHI));
                bLo[nj * 2][0] = d0; bLo[nj * 2][1] = d1;
                bLo[nj * 2 + 1][0] = d2; bLo[nj * 2 + 1][1] = d3;
            }
            #pragma unroll
            for (int mi = 0; mi < 2; ++mi)
                #pragma unroll
                for (int nf = 0; nf < 4; ++nf) {
                    mma16816(acc[mi][nf], aHi[mi], bHi[nf]);
                    mma16816(acc[mi][nf], aHi[mi], bLo[nf]);
                    mma16816(acc[mi][nf], aLo[mi], bHi[nf]);
                }
        }
    }

    // ---- epilogue: write to g_q/g_k/g_v in [H][M][D] layout ----
    const int part  = n0 >> 11;
    const int h     = (n0 >> 7) & 15;
    const int dbase = n0 & 64;
    float* dstp = (part == 0 ? g_q : (part == 1 ? g_k : g_v))
                  + (size_t)h * (M_TOK * D_HEAD);

    #pragma unroll
    for (int mi = 0; mi < 2; ++mi)
        #pragma unroll
        for (int nf = 0; nf < 4; ++nf) {
            int row = m0 + wm * 32 + mi * 16 + (lane >> 2);
            int col = dbase + wn * 32 + nf * 8 + (lane & 3) * 2;
            *(float2*)(dstp + (size_t)row * D_HEAD + col) =
                make_float2(acc[mi][nf][0], acc[mi][nf][1]);
            *(float2*)(dstp + (size_t)(row + 8) * D_HEAD + col) =
                make_float2(acc[mi][nf][2], acc[mi][nf][3]);
        }
}

// ============================================================
// Kernel 2: RMS norm rows of g_q and g_k (warp per row)
// ============================================================
__global__ __launch_bounds__(256) void rmsnorm_kernel()
{
    const int warp = threadIdx.x >> 5;
    const int lane = threadIdx.x & 31;
    const int row  = blockIdx.x * 8 + warp;
    float* base = (blockIdx.y == 0 ? g_q : g_k) + row * D_HEAD;

    float4 v = *(float4*)(base + lane * 4);
    float ss = v.x * v.x + v.y * v.y + v.z * v.z + v.w * v.w;
    #pragma unroll
    for (int off = 16; off > 0; off >>= 1)
        ss += __shfl_xor_sync(0xffffffffu, ss, off);
    float s = rsqrtf(ss * (1.0f / 128.0f));
    v.x *= s; v.y *= s; v.z *= s; v.w *= s;
    *(float4*)(base + lane * 4) = v;
}

// ============================================================
// Kernel 3: flash-style attention (plain exp, no max shift — matches ref)
// grid (M/128, H, 2 L-splits), 256 threads, Bq=128, BL=128, 8x8 tiles.
// ============================================================
#define ATTN_SMEM_FLOATS (128*128 + 128*128 + 128*130)

__global__ __launch_bounds__(256, 1) void attn_kernel(
    const float* __restrict__ cK, const float* __restrict__ cV,
    const int* __restrict__ Pp)
{
    extern __shared__ float smf[];
    float* Qs  = smf;                 // [128][128] k-major: Qs[d][m]
    float* KVs = smf + 128 * 128;     // K: [d][l], later V: [l][d]
    float* Ps  = smf + 2 * 128 * 128; // [m][l] pitch 130

    const int P  = Pp[0];
    const int t  = threadIdx.x;
    const int tx = t & 15;
    const int ty = t >> 4;
    const int h  = blockIdx.y;
    const int m0 = blockIdx.x * 128;
    const int z  = blockIdx.z;

    const float* qbase = g_q + (h * M_TOK + m0) * D_HEAD;
    #pragma unroll
    for (int it = 0; it < 16; ++it) {
        int idx = t + it * 256;
        int row = idx & 127;
        int dq  = (idx >> 7) * 4;
        float4 v = *(const float4*)(qbase + row * D_HEAD + dq);
        Qs[(dq + 0) * 128 + row] = v.x;
        Qs[(dq + 1) * 128 + row] = v.y;
        Qs[(dq + 2) * 128 + row] = v.z;
        Qs[(dq + 3) * 128 + row] = v.w;
    }

    float out_acc[8][8];
    #pragma unroll
    for (int i = 0; i < 8; ++i)
        #pragma unroll
        for (int j = 0; j < 8; ++j) out_acc[i][j] = 0.f;
    float den = 0.f;

    for (int ch = 0; ch < 16; ++ch) {
        const int l0 = z * 2048 + ch * 128;
        __syncthreads();

        #pragma unroll
        for (int it = 0; it < 16; ++it) {
            int idx = t + it * 256;
            int lr  = idx & 127;
            int dq  = (idx >> 7) * 4;
            int lg  = l0 + lr;
            const float* src = (lg >= P && lg < P + M_TOK)
                ? (g_k + (h * M_TOK + (lg - P)) * D_HEAD)
                : (cK + (h * L_CACHE + lg) * D_HEAD);
            float4 v = *(const float4*)(src + dq);
            KVs[(dq + 0) * 128 + lr] = v.x;
            KVs[(dq + 1) * 128 + lr] = v.y;
            KVs[(dq + 2) * 128 + lr] = v.z;
            KVs[(dq + 3) * 128 + lr] = v.w;
        }
        __syncthreads();

        float acc[8][8];
        #pragma unroll
        for (int i = 0; i < 8; ++i)
            #pragma unroll
            for (int j = 0; j < 8; ++j) acc[i][j] = 0.f;

        #pragma unroll 4
        for (int k = 0; k < 128; ++k) {
            float rq[8], rk[8];
            *(float4*)(rq)     = *(const float4*)(Qs + k * 128 + ty * 8);
            *(float4*)(rq + 4) = *(const float4*)(Qs + k * 128 + ty * 8 + 4);
            *(float4*)(rk)     = *(const float4*)(KVs + k * 128 + tx * 8);
            *(float4*)(rk + 4) = *(const float4*)(KVs + k * 128 + tx * 8 + 4);
            #pragma unroll
            for (int i = 0; i < 8; ++i)
                #pragma unroll
                for (int j = 0; j < 8; ++j)
                    acc[i][j] = fmaf(rq[i], rk[j], acc[i][j]);
        }

        #pragma unroll
        for (int i = 0; i < 8; ++i) {
            int m = ty * 8 + i;
            #pragma unroll
            for (int j = 0; j < 8; j += 2) {
                float2 e;
                e.x = __expf(acc[i][j]);
                e.y = __expf(acc[i][j + 1]);
                *(float2*)(Ps + m * 130 + tx * 8 + j) = e;
            }
        }
        __syncthreads();

        #pragma unroll
        for (int it = 0; it < 16; ++it) {
            int idx = t + it * 256;
            int lr  = idx >> 5;
            int dq  = (idx & 31) * 4;
            int lg  = l0 + lr;
            const float* src = (lg >= P && lg < P + M_TOK)
                ? (g_v + (h * M_TOK + (lg - P)) * D_HEAD)
                : (cV + (h * L_CACHE + lg) * D_HEAD);
            *(float4*)(KVs + lr * 128 + dq) = *(const float4*)(src + dq);
        }

        if (t < 128) {
            float s = 0.f;
            #pragma unroll 16
            for (int l = 0; l < 128; ++l) s += Ps[t * 130 + l];
            den += s;
        }
        __syncthreads();

        #pragma unroll 4
        for (int l = 0; l < 128; ++l) {
            float rp[8], rv[8];
            #pragma unroll
            for (int i = 0; i < 8; ++i) rp[i] = Ps[(ty * 8 + i) * 130 + l];
            *(float4*)(rv)     = *(const float4*)(KVs + l * 128 + tx * 8);
            *(float4*)(rv + 4) = *(const float4*)(KVs + l * 128 + tx * 8 + 4);
            #pragma unroll
            for (int i = 0; i < 8; ++i)
                #pragma unroll
                for (int j = 0; j < 8; ++j)
                    out_acc[i][j] = fmaf(rp[i], rv[j], out_acc[i][j]);
        }
    }

    float* po = g_po + ((size_t)(z * H_HEADS + h) * M_TOK + m0) * D_HEAD;
    #pragma unroll
    for (int i = 0; i < 8; ++i) {
        int m = ty * 8 + i;
        float4 v0 = make_float4(out_acc[i][0], out_acc[i][1], out_acc[i][2], out_acc[i][3]);
        float4 v1 = make_float4(out_acc[i][4], out_acc[i][5], out_acc[i][6], out_acc[i][7]);
        *(float4*)(po + m * D_HEAD + tx * 8)     = v0;
        *(float4*)(po + m * D_HEAD + tx * 8 + 4) = v1;
    }
    if (t < 128)
        g_pd[(z * H_HEADS + h) * M_TOK + m0 + t] = den;
}

// ============================================================
// Kernel 4: combine L-splits and write output [M, H*D]
// ============================================================
__global__ __launch_bounds__(256) void combine_kernel(float* __restrict__ out)
{
    int idx = blockIdx.x * 256 + threadIdx.x;
    int e = idx * 4;
    int d = e & 127;
    int m = (e >> 7) & 511;
    int h = e >> 16;

    float4 a = *(const float4*)(g_po + e);
    float4 b = *(const float4*)(g_po + H_HEADS * M_TOK * D_HEAD + e);
    float dn = g_pd[h * M_TOK + m] + g_pd[H_HEADS * M_TOK + h * M_TOK + m];
    float inv = 1.0f / dn;
    float4 r = make_float4((a.x + b.x) * inv, (a.y + b.y) * inv,
                           (a.z + b.z) * inv, (a.w + b.w) * inv);
    *(float4*)(out + m * N_DIM + h * D_HEAD + d) = r;
}

// ============================================================
extern "C" void kernel_launch(void* const* d_in, const int* in_sizes, int n_in,
                              void* d_out, int out_size)
{
    const float* X  = (const float*)d_in[0];
    const float* W  = (const float*)d_in[1];
    const float* cK = (const float*)d_in[2];
    const float* cV = (const float*)d_in[3];
    const int*   Pp = (const int*)d_in[4];
    float* out = (float*)d_out;

    const int attn_smem = ATTN_SMEM_FLOATS * sizeof(float); // ~193 KB
    cudaFuncSetAttribute(attn_kernel,
                         cudaFuncAttributeMaxDynamicSharedMemorySize, attn_smem);
    cudaFuncSetAttribute(qkv_mma_kernel,
                         cudaFuncAttributeMaxDynamicSharedMemorySize, GEMM_SMEM);

    convert_x_kernel<<<(M_TOK * N_DIM / 4) / 256, 256>>>(X);
    convert_w_kernel<<<dim3(N3 / 32, N_DIM / 32), dim3(32, 8)>>>(W);
    qkv_mma_kernel<<<dim3(N3 / 64, M_TOK / 128), 256, GEMM_SMEM>>>();
    rmsnorm_kernel<<<dim3((H_HEADS * M_TOK) / 8, 2), 256>>>();
    attn_kernel<<<dim3(M_TOK / 128, H_HEADS, 2), 256, attn_smem>>>(cK, cV, Pp);
    combine_kernel<<<(H_HEADS * M_TOK * D_HEAD / 4) / 256, 256>>>(out);
}

// round 7
// speedup vs baseline: 2.3992x; 1.1955x over previous
#include <cuda_runtime.h>
#include <cuda_bf16.h>
#include <cstdint>

// Problem dims (fixed by dataset)
#define M_TOK   512
#define N_DIM   2048
#define D_HEAD  128
#define H_HEADS 16
#define L_CACHE 4096
#define N3      6144   // 3*N_DIM

// -------- device scratch (no allocations allowed) --------
__device__ float g_q[H_HEADS * M_TOK * D_HEAD];   // [H][M][D]
__device__ float g_k[H_HEADS * M_TOK * D_HEAD];
__device__ float g_v[H_HEADS * M_TOK * D_HEAD];
__device__ float g_po[2 * H_HEADS * M_TOK * D_HEAD]; // partial numerators per L-split
__device__ float g_pd[2 * H_HEADS * M_TOK];           // partial denominators

// bf16x3 split operands for warp-MMA QKV GEMM
__device__ __nv_bfloat16 g_xhi[M_TOK * N_DIM];        // X  [m][k]
__device__ __nv_bfloat16 g_xlo[M_TOK * N_DIM];
__device__ __nv_bfloat16 g_wthi[(size_t)N3 * N_DIM];  // W^T [n][k]
__device__ __nv_bfloat16 g_wtlo[(size_t)N3 * N_DIM];

// ============================================================
// helpers
// ============================================================
__device__ __forceinline__ uint32_t smem_u32(const void* p) {
    uint32_t a;
    asm("{ .reg .u64 t; cvta.to.shared.u64 t, %1; cvt.u32.u64 %0, t; }"
        : "=r"(a) : "l"(p));
    return a;
}

__device__ __forceinline__ void ldm_x4(uint32_t& d0, uint32_t& d1,
                                       uint32_t& d2, uint32_t& d3, uint32_t addr) {
    asm volatile("ldmatrix.sync.aligned.m8n8.x4.shared.b16 {%0,%1,%2,%3}, [%4];"
                 : "=r"(d0), "=r"(d1), "=r"(d2), "=r"(d3) : "r"(addr));
}

__device__ __forceinline__ void mma16816(float* c, const uint32_t* a, const uint32_t* b) {
    asm volatile(
        "mma.sync.aligned.m16n8k16.row.col.f32.bf16.bf16.f32 "
        "{%0,%1,%2,%3}, {%4,%5,%6,%7}, {%8,%9}, {%0,%1,%2,%3};"
        : "+f"(c[0]), "+f"(c[1]), "+f"(c[2]), "+f"(c[3])
        : "r"(a[0]), "r"(a[1]), "r"(a[2]), "r"(a[3]), "r"(b[0]), "r"(b[1]));
}

__device__ __forceinline__ void split_bf16(float x, __nv_bfloat16& hi, __nv_bfloat16& lo) {
    hi = __float2bfloat16_rn(x);
    lo = __float2bfloat16_rn(x - __bfloat162float(hi));
}

__device__ __forceinline__ uint32_t pack2(__nv_bfloat16 a, __nv_bfloat16 b) {
    return (uint32_t)__bfloat16_as_ushort(a) | ((uint32_t)__bfloat16_as_ushort(b) << 16);
}

// ============================================================
// Kernel 0a: split X -> g_xhi/g_xlo  [m][k]
// ============================================================
__global__ __launch_bounds__(256) void convert_x_kernel(const float* __restrict__ X)
{
    int idx = blockIdx.x * 256 + threadIdx.x;      // float4 index, 262144 total
    float4 v = *(const float4*)(X + idx * 4);
    __nv_bfloat16 h0, l0, h1, l1, h2, l2, h3, l3;
    split_bf16(v.x, h0, l0); split_bf16(v.y, h1, l1);
    split_bf16(v.z, h2, l2); split_bf16(v.w, h3, l3);
    __nv_bfloat162* ph = (__nv_bfloat162*)(g_xhi + idx * 4);
    __nv_bfloat162* pl = (__nv_bfloat162*)(g_xlo + idx * 4);
    ph[0] = __nv_bfloat162(h0, h1); ph[1] = __nv_bfloat162(h2, h3);
    pl[0] = __nv_bfloat162(l0, l1); pl[1] = __nv_bfloat162(l2, l3);
}

// ============================================================
// Kernel 0b: transpose+split W[k][n] -> g_wthi/g_wtlo [n][k]
// ============================================================
__global__ __launch_bounds__(256) void convert_w_kernel(const float* __restrict__ W)
{
    __shared__ float tile[32][33];
    const int n0 = blockIdx.x * 32;
    const int k0 = blockIdx.y * 32;
    const int tx = threadIdx.x, ty = threadIdx.y;

    #pragma unroll
    for (int l = 0; l < 4; ++l)
        tile[ty * 4 + l][tx] = W[(size_t)(k0 + ty * 4 + l) * N3 + n0 + tx];
    __syncthreads();

    #pragma unroll
    for (int l = 0; l < 4; ++l) {
        int nl = ty * 4 + l;
        float x = tile[tx][nl];
        __nv_bfloat16 hi, lo;
        split_bf16(x, hi, lo);
        size_t o = (size_t)(n0 + nl) * N_DIM + k0 + tx;
        g_wthi[o] = hi;
        g_wtlo[o] = lo;
    }
}

// ============================================================
// Kernel 1: QKV GEMM via mma.sync bf16x3 (hi*hi + hi*lo + lo*hi)
// BM=128, BN=64, BK=32; 256 thr = 8 warps (4x2), warp tile 32x32.
// ============================================================
#define PITCH_E   40
#define PITCH_B   80
#define A_TILE_B  (128 * PITCH_B)   // 10240
#define B_TILE_B  (64  * PITCH_B)   // 5120
#define OFF_AHI   0
#define OFF_ALO   A_TILE_B
#define OFF_BHI   (2 * A_TILE_B)
#define OFF_BLO   (2 * A_TILE_B + B_TILE_B)
#define BUF_B     (2 * A_TILE_B + 2 * B_TILE_B)   // 30720
#define GEMM_SMEM (2 * BUF_B)                     // 61440

__global__ __launch_bounds__(256) void qkv_mma_kernel()
{
    extern __shared__ __align__(128) char sm[];
    const uint32_t sb = smem_u32(sm);
    const int t    = threadIdx.x;
    const int lane = t & 31;
    const int wid  = t >> 5;
    const int wm   = wid & 3;        // 0..3  (m-warp)
    const int wn   = wid >> 2;       // 0..1  (n-warp)
    const int lg   = lane >> 3;      // ldmatrix group 0..3
    const int lr   = lane & 7;
    const int m0   = blockIdx.y * 128;
    const int n0   = blockIdx.x * 64;

    auto load_tiles = [&](int k0, int buf) {
        char* base = sm + buf * BUF_B;
        #pragma unroll
        for (int i = 0; i < 6; ++i) {
            int idx = t + i * 256;                 // 0..1535 16B chunks
            const __nv_bfloat16* gsrc;
            int local, off;
            if (idx < 512)       { gsrc = g_xhi  + (size_t)m0 * N_DIM; local = idx;        off = OFF_AHI; }
            else if (idx < 1024) { gsrc = g_xlo  + (size_t)m0 * N_DIM; local = idx - 512;  off = OFF_ALO; }
            else if (idx < 1280) { gsrc = g_wthi + (size_t)n0 * N_DIM; local = idx - 1024; off = OFF_BHI; }
            else                 { gsrc = g_wtlo + (size_t)n0 * N_DIM; local = idx - 1280; off = OFF_BLO; }
            int r = local >> 2, c = local & 3;
            uint4 v = *(const uint4*)(gsrc + (size_t)r * N_DIM + k0 + c * 8);
            *(uint4*)(base + off + r * PITCH_B + c * 16) = v;
        }
    };

    float acc[2][4][4];
    #pragma unroll
    for (int mi = 0; mi < 2; ++mi)
        #pragma unroll
        for (int nf = 0; nf < 4; ++nf)
            #pragma unroll
            for (int e = 0; e < 4; ++e) acc[mi][nf][e] = 0.f;

    load_tiles(0, 0);

    const int NIT = N_DIM / 32;    // 64
    for (int it = 0; it < NIT; ++it) {
        const int buf = it & 1;
        __syncthreads();
        if (it + 1 < NIT) load_tiles((it + 1) * 32, buf ^ 1);

        const uint32_t bb = sb + buf * BUF_B;
        #pragma unroll
        for (int ks = 0; ks < 2; ++ks) {
            uint32_t aHi[2][4], aLo[2][4], bHi[4][2], bLo[4][2];
            #pragma unroll
            for (int mi = 0; mi < 2; ++mi) {
                int row = wm * 32 + mi * 16 + lr + (lg & 1) * 8;
                int col = ks * 16 + (lg >> 1) * 8;
                uint32_t ad = bb + OFF_AHI + row * PITCH_B + col * 2;
                ldm_x4(aHi[mi][0], aHi[mi][1], aHi[mi][2], aHi[mi][3], ad);
                ldm_x4(aLo[mi][0], aLo[mi][1], aLo[mi][2], aLo[mi][3], ad + (OFF_ALO - OFF_AHI));
            }
            #pragma unroll
            for (int nj = 0; nj < 2; ++nj) {
                int row = wn * 32 + nj * 16 + (lg >> 1) * 8 + lr;
                int col = ks * 16 + (lg & 1) * 8;
                uint32_t bd = bb + OFF_BHI + row * PITCH_B + col * 2;
                uint32_t d0, d1, d2, d3;
                ldm_x4(d0, d1, d2, d3, bd);
                bHi[nj * 2][0] = d0; bHi[nj * 2][1] = d1;
                bHi[nj * 2 + 1][0] = d2; bHi[nj * 2 + 1][1] = d3;
                ldm_x4(d0, d1, d2, d3, bd + (OFF_BLO - OFF_BHI));
                bLo[nj * 2][0] = d0; bLo[nj * 2][1] = d1;
                bLo[nj * 2 + 1][0] = d2; bLo[nj * 2 + 1][1] = d3;
            }
            #pragma unroll
            for (int mi = 0; mi < 2; ++mi)
                #pragma unroll
                for (int nf = 0; nf < 4; ++nf) {
                    mma16816(acc[mi][nf], aHi[mi], bHi[nf]);
                    mma16816(acc[mi][nf], aHi[mi], bLo[nf]);
                    mma16816(acc[mi][nf], aLo[mi], bHi[nf]);
                }
        }
    }

    const int part  = n0 >> 11;
    const int h     = (n0 >> 7) & 15;
    const int dbase = n0 & 64;
    float* dstp = (part == 0 ? g_q : (part == 1 ? g_k : g_v))
                  + (size_t)h * (M_TOK * D_HEAD);

    #pragma unroll
    for (int mi = 0; mi < 2; ++mi)
        #pragma unroll
        for (int nf = 0; nf < 4; ++nf) {
            int row = m0 + wm * 32 + mi * 16 + (lane >> 2);
            int col = dbase + wn * 32 + nf * 8 + (lane & 3) * 2;
            *(float2*)(dstp + (size_t)row * D_HEAD + col) =
                make_float2(acc[mi][nf][0], acc[mi][nf][1]);
            *(float2*)(dstp + (size_t)(row + 8) * D_HEAD + col) =
                make_float2(acc[mi][nf][2], acc[mi][nf][3]);
        }
}

// ============================================================
// Kernel 2: RMS norm rows of g_q and g_k (warp per row)
// ============================================================
__global__ __launch_bounds__(256) void rmsnorm_kernel()
{
    const int warp = threadIdx.x >> 5;
    const int lane = threadIdx.x & 31;
    const int row  = blockIdx.x * 8 + warp;
    float* base = (blockIdx.y == 0 ? g_q : g_k) + row * D_HEAD;

    float4 v = *(float4*)(base + lane * 4);
    float ss = v.x * v.x + v.y * v.y + v.z * v.z + v.w * v.w;
    #pragma unroll
    for (int off = 16; off > 0; off >>= 1)
        ss += __shfl_xor_sync(0xffffffffu, ss, off);
    float s = rsqrtf(ss * (1.0f / 128.0f));
    v.x *= s; v.y *= s; v.z *= s; v.w *= s;
    *(float4*)(base + lane * 4) = v;
}

// ============================================================
// Kernel 3: hybrid attention.
//   S = Q K^T on mma.sync bf16x3 (Q,K split hi/lo in smem)
//   exp on MUFU; P stored fp32 to smem (aliases K region)
//   out += P V in fp32 SIMT (V fp32 in smem)
// grid (4, 16, 2), 256 thr = 8 warps (4m x 2n), chunk CL=64.
// ============================================================
#define CL        64
#define QP_B      272                   // Q/K row pitch bytes (136 bf16)
#define Q_HI_OFF  0
#define Q_LO_OFF  (128 * QP_B)          // 34816
#define KAREA_OFF (2 * 128 * QP_B)      // 69632
#define K_LO_REL  (CL * QP_B)           // 17408
#define V_OFF     (KAREA_OFF + 2 * CL * QP_B)  // 104448
#define ATTN_SMEM_B (V_OFF + CL * 128 * 4)     // 137216

__global__ __launch_bounds__(256, 1) void attn_kernel(
    const float* __restrict__ cK, const float* __restrict__ cV,
    const int* __restrict__ Pp)
{
    extern __shared__ __align__(128) char sm[];
    const uint32_t sb = smem_u32(sm);
    float* Ps = (float*)(sm + KAREA_OFF);   // [128][66] fp32, aliases K tiles
    float* Vs = (float*)(sm + V_OFF);       // [64][128] fp32

    const int P    = Pp[0];
    const int t    = threadIdx.x;
    const int lane = t & 31;
    const int wid  = t >> 5;
    const int wm   = wid & 3;
    const int wn   = wid >> 2;
    const int lr   = lane & 7;
    const int lg   = lane >> 3;
    const int tx   = t & 15;
    const int ty   = t >> 4;
    const int h    = blockIdx.y;
    const int m0   = blockIdx.x * 128;
    const int z    = blockIdx.z;

    // ---- load Q tile, split to bf16 hi/lo ----
    const float* qbase = g_q + (h * M_TOK + m0) * D_HEAD;
    #pragma unroll
    for (int i = 0; i < 16; ++i) {
        int idx = t + i * 256;         // 0..4095 float4
        int row = idx >> 5;
        int c4  = idx & 31;
        float4 v = *(const float4*)(qbase + row * 128 + c4 * 4);
        __nv_bfloat16 h0, l0, h1, l1, h2, l2, h3, l3;
        split_bf16(v.x, h0, l0); split_bf16(v.y, h1, l1);
        split_bf16(v.z, h2, l2); split_bf16(v.w, h3, l3);
        *(uint2*)(sm + Q_HI_OFF + row * QP_B + c4 * 8) = make_uint2(pack2(h0, h1), pack2(h2, h3));
        *(uint2*)(sm + Q_LO_OFF + row * QP_B + c4 * 8) = make_uint2(pack2(l0, l1), pack2(l2, l3));
    }

    float out_acc[8][8];
    #pragma unroll
    for (int i = 0; i < 8; ++i)
        #pragma unroll
        for (int j = 0; j < 8; ++j) out_acc[i][j] = 0.f;
    float den = 0.f;

    for (int ch = 0; ch < 2048 / CL; ++ch) {
        const int l0 = z * 2048 + ch * CL;
        __syncthreads();   // prev PV done reading Ps(K area) and Vs

        // ---- load K chunk (split bf16 hi/lo) and V chunk (fp32) ----
        #pragma unroll
        for (int i = 0; i < 8; ++i) {
            int idx = t + i * 256;       // 0..2047 float4
            int row = idx >> 5;          // 0..63
            int c4  = idx & 31;
            int lg_ = l0 + row;
            const float* srcK = (lg_ >= P && lg_ < P + M_TOK)
                ? (g_k + (h * M_TOK + (lg_ - P)) * D_HEAD)
                : (cK + (h * L_CACHE + lg_) * D_HEAD);
            float4 v = *(const float4*)(srcK + c4 * 4);
            __nv_bfloat16 h0, l0b, h1, l1b, h2, l2b, h3, l3b;
            split_bf16(v.x, h0, l0b); split_bf16(v.y, h1, l1b);
            split_bf16(v.z, h2, l2b); split_bf16(v.w, h3, l3b);
            *(uint2*)(sm + KAREA_OFF + row * QP_B + c4 * 8) =
                make_uint2(pack2(h0, h1), pack2(h2, h3));
            *(uint2*)(sm + KAREA_OFF + K_LO_REL + row * QP_B + c4 * 8) =
                make_uint2(pack2(l0b, l1b), pack2(l2b, l3b));
            const float* srcV = (lg_ >= P && lg_ < P + M_TOK)
                ? (g_v + (h * M_TOK + (lg_ - P)) * D_HEAD)
                : (cV + (h * L_CACHE + lg_) * D_HEAD);
            *(float4*)(Vs + row * 128 + c4 * 4) = *(const float4*)(srcV + c4 * 4);
        }
        __syncthreads();

        // ---- S = Q K^T via mma.sync bf16x3 ----
        float s[2][4][4];
        #pragma unroll
        for (int mi = 0; mi < 2; ++mi)
            #pragma unroll
            for (int nj = 0; nj < 4; ++nj)
                #pragma unroll
                for (int e = 0; e < 4; ++e) s[mi][nj][e] = 0.f;

        #pragma unroll
        for (int ks = 0; ks < 8; ++ks) {
            uint32_t aHi[2][4], aLo[2][4], bHi[4][2], bLo[4][2];
            #pragma unroll
            for (int mi = 0; mi < 2; ++mi) {
                int row = wm * 32 + mi * 16 + lr + (lg & 1) * 8;
                uint32_t ad = sb + Q_HI_OFF + row * QP_B + ks * 32 + (lg >> 1) * 16;
                ldm_x4(aHi[mi][0], aHi[mi][1], aHi[mi][2], aHi[mi][3], ad);
                ldm_x4(aLo[mi][0], aLo[mi][1], aLo[mi][2], aLo[mi][3], ad + Q_LO_OFF);
            }
            #pragma unroll
            for (int ng = 0; ng < 2; ++ng) {
                int row = wn * 32 + ng * 16 + (lg >> 1) * 8 + lr;
                uint32_t bd = sb + KAREA_OFF + row * QP_B + ks * 32 + (lg & 1) * 16;
                uint32_t d0, d1, d2, d3;
                ldm_x4(d0, d1, d2, d3, bd);
                bHi[ng * 2][0] = d0; bHi[ng * 2][1] = d1;
                bHi[ng * 2 + 1][0] = d2; bHi[ng * 2 + 1][1] = d3;
                ldm_x4(d0, d1, d2, d3, bd + K_LO_REL);
                bLo[ng * 2][0] = d0; bLo[ng * 2][1] = d1;
                bLo[ng * 2 + 1][0] = d2; bLo[ng * 2 + 1][1] = d3;
            }
            #pragma unroll
            for (int mi = 0; mi < 2; ++mi)
                #pragma unroll
                for (int nj = 0; nj < 4; ++nj) {
                    mma16816(s[mi][nj], aHi[mi], bHi[nj]);
                    mma16816(s[mi][nj], aHi[mi], bLo[nj]);
                    mma16816(s[mi][nj], aLo[mi], bHi[nj]);
                }
        }

        // exp in registers
        #pragma unroll
        for (int mi = 0; mi < 2; ++mi)
            #pragma unroll
            for (int nj = 0; nj < 4; ++nj)
                #pragma unroll
                for (int e = 0; e < 4; ++e) s[mi][nj][e] = __expf(s[mi][nj][e]);

        __syncthreads();   // all warps done reading K tiles (Ps aliases them)

        // store P (fp32) to Ps [128][66]
        {
            int r0 = wm * 32 + (lane >> 2);
            int c0 = wn * 32 + (lane & 3) * 2;
            #pragma unroll
            for (int mi = 0; mi < 2; ++mi)
                #pragma unroll
                for (int nj = 0; nj < 4; ++nj) {
                    int row = r0 + mi * 16;
                    int col = c0 + nj * 8;
                    *(float2*)(Ps + row * 66 + col) = make_float2(s[mi][nj][0], s[mi][nj][1]);
                    *(float2*)(Ps + (row + 8) * 66 + col) = make_float2(s[mi][nj][2], s[mi][nj][3]);
                }
        }
        __syncthreads();

        // denominator partial
        if (t < 128) {
            float sd = 0.f;
            #pragma unroll 16
            for (int l = 0; l < CL; ++l) sd += Ps[t * 66 + l];
            den += sd;
        }

        // out += P V  (fp32 SIMT, 8x8 per thread)
        #pragma unroll 4
        for (int l = 0; l < CL; ++l) {
            float rp[8], rv[8];
            #pragma unroll
            for (int i = 0; i < 8; ++i) rp[i] = Ps[(ty * 8 + i) * 66 + l];
            *(float4*)(rv)     = *(const float4*)(Vs + l * 128 + tx * 8);
            *(float4*)(rv + 4) = *(const float4*)(Vs + l * 128 + tx * 8 + 4);
            #pragma unroll
            for (int i = 0; i < 8; ++i)
                #pragma unroll
                for (int j = 0; j < 8; ++j)
                    out_acc[i][j] = fmaf(rp[i], rv[j], out_acc[i][j]);
        }
    }

    // write partial numerator / denominator
    float* po = g_po + ((size_t)(z * H_HEADS + h) * M_TOK + m0) * D_HEAD;
    #pragma unroll
    for (int i = 0; i < 8; ++i) {
        int m = ty * 8 + i;
        float4 v0 = make_float4(out_acc[i][0], out_acc[i][1], out_acc[i][2], out_acc[i][3]);
        float4 v1 = make_float4(out_acc[i][4], out_acc[i][5], out_acc[i][6], out_acc[i][7]);
        *(float4*)(po + m * D_HEAD + tx * 8)     = v0;
        *(float4*)(po + m * D_HEAD + tx * 8 + 4) = v1;
    }
    if (t < 128)
        g_pd[(z * H_HEADS + h) * M_TOK + m0 + t] = den;
}

// ============================================================
// Kernel 4: combine L-splits and write output [M, H*D]
// ============================================================
__global__ __launch_bounds__(256) void combine_kernel(float* __restrict__ out)
{
    int idx = blockIdx.x * 256 + threadIdx.x;
    int e = idx * 4;
    int d = e & 127;
    int m = (e >> 7) & 511;
    int h = e >> 16;

    float4 a = *(const float4*)(g_po + e);
    float4 b = *(const float4*)(g_po + H_HEADS * M_TOK * D_HEAD + e);
    float dn = g_pd[h * M_TOK + m] + g_pd[H_HEADS * M_TOK + h * M_TOK + m];
    float inv = 1.0f / dn;
    float4 r = make_float4((a.x + b.x) * inv, (a.y + b.y) * inv,
                           (a.z + b.z) * inv, (a.w + b.w) * inv);
    *(float4*)(out + m * N_DIM + h * D_HEAD + d) = r;
}

// ============================================================
extern "C" void kernel_launch(void* const* d_in, const int* in_sizes, int n_in,
                              void* d_out, int out_size)
{
    const float* X  = (const float*)d_in[0];
    const float* W  = (const float*)d_in[1];
    const float* cK = (const float*)d_in[2];
    const float* cV = (const float*)d_in[3];
    const int*   Pp = (const int*)d_in[4];
    float* out = (float*)d_out;

    cudaFuncSetAttribute(attn_kernel,
                         cudaFuncAttributeMaxDynamicSharedMemorySize, ATTN_SMEM_B);
    cudaFuncSetAttribute(qkv_mma_kernel,
                         cudaFuncAttributeMaxDynamicSharedMemorySize, GEMM_SMEM);

    convert_x_kernel<<<(M_TOK * N_DIM / 4) / 256, 256>>>(X);
    convert_w_kernel<<<dim3(N3 / 32, N_DIM / 32), dim3(32, 8)>>>(W);
    qkv_mma_kernel<<<dim3(N3 / 64, M_TOK / 128), 256, GEMM_SMEM>>>();
    rmsnorm_kernel<<<dim3((H_HEADS * M_TOK) / 8, 2), 256>>>();
    attn_kernel<<<dim3(M_TOK / 128, H_HEADS, 2), 256, ATTN_SMEM_B>>>(cK, cV, Pp);
    combine_kernel<<<(H_HEADS * M_TOK * D_HEAD / 4) / 256, 256>>>(out);
}

// round 8
// speedup vs baseline: 3.2489x; 1.3541x over previous
#include <cuda_runtime.h>
#include <cuda_bf16.h>
#include <cstdint>

// Problem dims (fixed by dataset)
#define M_TOK   512
#define N_DIM   2048
#define D_HEAD  128
#define H_HEADS 16
#define L_CACHE 4096
#define N3      6144   // 3*N_DIM

// -------- device scratch (no allocations allowed) --------
__device__ float g_q[H_HEADS * M_TOK * D_HEAD];   // [H][M][D]
__device__ float g_k[H_HEADS * M_TOK * D_HEAD];
__device__ float g_v[H_HEADS * M_TOK * D_HEAD];
__device__ float g_po[2 * H_HEADS * M_TOK * D_HEAD]; // partial numerators per L-split
__device__ float g_pd[2 * H_HEADS * M_TOK];           // partial denominators

// bf16x3 split operands for warp-MMA QKV GEMM
__device__ __nv_bfloat16 g_xhi[M_TOK * N_DIM];        // X  [m][k]
__device__ __nv_bfloat16 g_xlo[M_TOK * N_DIM];
__device__ __nv_bfloat16 g_wthi[(size_t)N3 * N_DIM];  // W^T [n][k]
__device__ __nv_bfloat16 g_wtlo[(size_t)N3 * N_DIM];

// ============================================================
// helpers
// ============================================================
__device__ __forceinline__ uint32_t smem_u32(const void* p) {
    uint32_t a;
    asm("{ .reg .u64 t; cvta.to.shared.u64 t, %1; cvt.u32.u64 %0, t; }"
        : "=r"(a) : "l"(p));
    return a;
}

__device__ __forceinline__ void ldm_x4(uint32_t& d0, uint32_t& d1,
                                       uint32_t& d2, uint32_t& d3, uint32_t addr) {
    asm volatile("ldmatrix.sync.aligned.m8n8.x4.shared.b16 {%0,%1,%2,%3}, [%4];"
                 : "=r"(d0), "=r"(d1), "=r"(d2), "=r"(d3) : "r"(addr));
}

__device__ __forceinline__ void ldm_x4_t(uint32_t& d0, uint32_t& d1,
                                         uint32_t& d2, uint32_t& d3, uint32_t addr) {
    asm volatile("ldmatrix.sync.aligned.m8n8.x4.trans.shared.b16 {%0,%1,%2,%3}, [%4];"
                 : "=r"(d0), "=r"(d1), "=r"(d2), "=r"(d3) : "r"(addr));
}

__device__ __forceinline__ void mma16816(float* c, const uint32_t* a, const uint32_t* b) {
    asm volatile(
        "mma.sync.aligned.m16n8k16.row.col.f32.bf16.bf16.f32 "
        "{%0,%1,%2,%3}, {%4,%5,%6,%7}, {%8,%9}, {%0,%1,%2,%3};"
        : "+f"(c[0]), "+f"(c[1]), "+f"(c[2]), "+f"(c[3])
        : "r"(a[0]), "r"(a[1]), "r"(a[2]), "r"(a[3]), "r"(b[0]), "r"(b[1]));
}

__device__ __forceinline__ void split_bf16(float x, __nv_bfloat16& hi, __nv_bfloat16& lo) {
    hi = __float2bfloat16_rn(x);
    lo = __float2bfloat16_rn(x - __bfloat162float(hi));
}

__device__ __forceinline__ uint32_t pack2(__nv_bfloat16 a, __nv_bfloat16 b) {
    return (uint32_t)__bfloat16_as_ushort(a) | ((uint32_t)__bfloat16_as_ushort(b) << 16);
}

// ============================================================
// Kernel 0a: split X -> g_xhi/g_xlo  [m][k]
// ============================================================
__global__ __launch_bounds__(256) void convert_x_kernel(const float* __restrict__ X)
{
    int idx = blockIdx.x * 256 + threadIdx.x;      // float4 index, 262144 total
    float4 v = *(const float4*)(X + idx * 4);
    __nv_bfloat16 h0, l0, h1, l1, h2, l2, h3, l3;
    split_bf16(v.x, h0, l0); split_bf16(v.y, h1, l1);
    split_bf16(v.z, h2, l2); split_bf16(v.w, h3, l3);
    __nv_bfloat162* ph = (__nv_bfloat162*)(g_xhi + idx * 4);
    __nv_bfloat162* pl = (__nv_bfloat162*)(g_xlo + idx * 4);
    ph[0] = __nv_bfloat162(h0, h1); ph[1] = __nv_bfloat162(h2, h3);
    pl[0] = __nv_bfloat162(l0, l1); pl[1] = __nv_bfloat162(l2, l3);
}

// ============================================================
// Kernel 0b: transpose+split W[k][n] -> g_wthi/g_wtlo [n][k]
// ============================================================
__global__ __launch_bounds__(256) void convert_w_kernel(const float* __restrict__ W)
{
    __shared__ float tile[32][33];
    const int n0 = blockIdx.x * 32;
    const int k0 = blockIdx.y * 32;
    const int tx = threadIdx.x, ty = threadIdx.y;

    #pragma unroll
    for (int l = 0; l < 4; ++l)
        tile[ty * 4 + l][tx] = W[(size_t)(k0 + ty * 4 + l) * N3 + n0 + tx];
    __syncthreads();

    #pragma unroll
    for (int l = 0; l < 4; ++l) {
        int nl = ty * 4 + l;
        float x = tile[tx][nl];
        __nv_bfloat16 hi, lo;
        split_bf16(x, hi, lo);
        size_t o = (size_t)(n0 + nl) * N_DIM + k0 + tx;
        g_wthi[o] = hi;
        g_wtlo[o] = lo;
    }
}

// ============================================================
// Kernel 1: QKV GEMM via mma.sync bf16x3 (hi*hi + hi*lo + lo*hi)
// BM=128, BN=64, BK=32; 256 thr = 8 warps (4x2), warp tile 32x32.
// ============================================================
#define PITCH_B   80
#define A_TILE_B  (128 * PITCH_B)   // 10240
#define B_TILE_B  (64  * PITCH_B)   // 5120
#define OFF_AHI   0
#define OFF_ALO   A_TILE_B
#define OFF_BHI   (2 * A_TILE_B)
#define OFF_BLO   (2 * A_TILE_B + B_TILE_B)
#define BUF_B     (2 * A_TILE_B + 2 * B_TILE_B)   // 30720
#define GEMM_SMEM (2 * BUF_B)                     // 61440

__global__ __launch_bounds__(256) void qkv_mma_kernel()
{
    extern __shared__ __align__(128) char sm[];
    const uint32_t sb = smem_u32(sm);
    const int t    = threadIdx.x;
    const int lane = t & 31;
    const int wid  = t >> 5;
    const int wm   = wid & 3;        // 0..3  (m-warp)
    const int wn   = wid >> 2;       // 0..1  (n-warp)
    const int lg   = lane >> 3;      // ldmatrix group 0..3
    const int lr   = lane & 7;
    const int m0   = blockIdx.y * 128;
    const int n0   = blockIdx.x * 64;

    auto load_tiles = [&](int k0, int buf) {
        char* base = sm + buf * BUF_B;
        #pragma unroll
        for (int i = 0; i < 6; ++i) {
            int idx = t + i * 256;                 // 0..1535 16B chunks
            const __nv_bfloat16* gsrc;
            int local, off;
            if (idx < 512)       { gsrc = g_xhi  + (size_t)m0 * N_DIM; local = idx;        off = OFF_AHI; }
            else if (idx < 1024) { gsrc = g_xlo  + (size_t)m0 * N_DIM; local = idx - 512;  off = OFF_ALO; }
            else if (idx < 1280) { gsrc = g_wthi + (size_t)n0 * N_DIM; local = idx - 1024; off = OFF_BHI; }
            else                 { gsrc = g_wtlo + (size_t)n0 * N_DIM; local = idx - 1280; off = OFF_BLO; }
            int r = local >> 2, c = local & 3;
            uint4 v = *(const uint4*)(gsrc + (size_t)r * N_DIM + k0 + c * 8);
            *(uint4*)(base + off + r * PITCH_B + c * 16) = v;
        }
    };

    float acc[2][4][4];
    #pragma unroll
    for (int mi = 0; mi < 2; ++mi)
        #pragma unroll
        for (int nf = 0; nf < 4; ++nf)
            #pragma unroll
            for (int e = 0; e < 4; ++e) acc[mi][nf][e] = 0.f;

    load_tiles(0, 0);

    const int NIT = N_DIM / 32;    // 64
    for (int it = 0; it < NIT; ++it) {
        const int buf = it & 1;
        __syncthreads();
        if (it + 1 < NIT) load_tiles((it + 1) * 32, buf ^ 1);

        const uint32_t bb = sb + buf * BUF_B;
        #pragma unroll
        for (int ks = 0; ks < 2; ++ks) {
            uint32_t aHi[2][4], aLo[2][4], bHi[4][2], bLo[4][2];
            #pragma unroll
            for (int mi = 0; mi < 2; ++mi) {
                int row = wm * 32 + mi * 16 + lr + (lg & 1) * 8;
                int col = ks * 16 + (lg >> 1) * 8;
                uint32_t ad = bb + OFF_AHI + row * PITCH_B + col * 2;
                ldm_x4(aHi[mi][0], aHi[mi][1], aHi[mi][2], aHi[mi][3], ad);
                ldm_x4(aLo[mi][0], aLo[mi][1], aLo[mi][2], aLo[mi][3], ad + (OFF_ALO - OFF_AHI));
            }
            #pragma unroll
            for (int nj = 0; nj < 2; ++nj) {
                int row = wn * 32 + nj * 16 + (lg >> 1) * 8 + lr;
                int col = ks * 16 + (lg & 1) * 8;
                uint32_t bd = bb + OFF_BHI + row * PITCH_B + col * 2;
                uint32_t d0, d1, d2, d3;
                ldm_x4(d0, d1, d2, d3, bd);
                bHi[nj * 2][0] = d0; bHi[nj * 2][1] = d1;
                bHi[nj * 2 + 1][0] = d2; bHi[nj * 2 + 1][1] = d3;
                ldm_x4(d0, d1, d2, d3, bd + (OFF_BLO - OFF_BHI));
                bLo[nj * 2][0] = d0; bLo[nj * 2][1] = d1;
                bLo[nj * 2 + 1][0] = d2; bLo[nj * 2 + 1][1] = d3;
            }
            #pragma unroll
            for (int mi = 0; mi < 2; ++mi)
                #pragma unroll
                for (int nf = 0; nf < 4; ++nf) {
                    mma16816(acc[mi][nf], aHi[mi], bHi[nf]);
                    mma16816(acc[mi][nf], aHi[mi], bLo[nf]);
                    mma16816(acc[mi][nf], aLo[mi], bHi[nf]);
                }
        }
    }

    const int part  = n0 >> 11;
    const int h     = (n0 >> 7) & 15;
    const int dbase = n0 & 64;
    float* dstp = (part == 0 ? g_q : (part == 1 ? g_k : g_v))
                  + (size_t)h * (M_TOK * D_HEAD);

    #pragma unroll
    for (int mi = 0; mi < 2; ++mi)
        #pragma unroll
        for (int nf = 0; nf < 4; ++nf) {
            int row = m0 + wm * 32 + mi * 16 + (lane >> 2);
            int col = dbase + wn * 32 + nf * 8 + (lane & 3) * 2;
            *(float2*)(dstp + (size_t)row * D_HEAD + col) =
                make_float2(acc[mi][nf][0], acc[mi][nf][1]);
            *(float2*)(dstp + (size_t)(row + 8) * D_HEAD + col) =
                make_float2(acc[mi][nf][2], acc[mi][nf][3]);
        }
}

// ============================================================
// Kernel 2: RMS norm rows of g_q and g_k (warp per row)
// ============================================================
__global__ __launch_bounds__(256) void rmsnorm_kernel()
{
    const int warp = threadIdx.x >> 5;
    const int lane = threadIdx.x & 31;
    const int row  = blockIdx.x * 8 + warp;
    float* base = (blockIdx.y == 0 ? g_q : g_k) + row * D_HEAD;

    float4 v = *(float4*)(base + lane * 4);
    float ss = v.x * v.x + v.y * v.y + v.z * v.z + v.w * v.w;
    #pragma unroll
    for (int off = 16; off > 0; off >>= 1)
        ss += __shfl_xor_sync(0xffffffffu, ss, off);
    float s = rsqrtf(ss * (1.0f / 128.0f));
    v.x *= s; v.y *= s; v.z *= s; v.w *= s;
    *(float4*)(base + lane * 4) = v;
}

// ============================================================
// Kernel 3: full-tensor attention.
//   S = Q K^T  via mma.sync bf16x3
//   exp in registers; P split hi/lo -> smem bf16
//   out += P V via mma.sync bf16x3 (V split hi/lo, ldmatrix.trans)
// grid (4, 16, 2), 256 thr = 8 warps (4m x 2n), chunk CL=64.
// ============================================================
#define CL        64
#define QP_B      272                        // 128 bf16 + 8 pad
#define PSP_B     144                        // 64 bf16 + 8 pad
#define Q_HI_OFF  0
#define Q_LO_OFF  (128 * QP_B)               // 34816
#define K_HI_OFF  (2 * 128 * QP_B)           // 69632
#define K_LO_OFF  (K_HI_OFF + CL * QP_B)     // 87040
#define V_HI_OFF  (K_LO_OFF + CL * QP_B)     // 104448
#define V_LO_OFF  (V_HI_OFF + CL * QP_B)     // 121856
#define PS_HI_OFF (V_LO_OFF + CL * QP_B)     // 139264
#define PS_LO_OFF (PS_HI_OFF + 128 * PSP_B)  // 157696
#define DEN_OFF   (PS_LO_OFF + 128 * PSP_B)  // 176128
#define ATTN_SMEM_B (DEN_OFF + 2 * 128 * 4)  // 177152

__global__ __launch_bounds__(256, 1) void attn_kernel(
    const float* __restrict__ cK, const float* __restrict__ cV,
    const int* __restrict__ Pp)
{
    extern __shared__ __align__(128) char sm[];
    const uint32_t sb = smem_u32(sm);
    float* denb = (float*)(sm + DEN_OFF);   // [2][128]

    const int P    = Pp[0];
    const int t    = threadIdx.x;
    const int lane = t & 31;
    const int wid  = t >> 5;
    const int wm   = wid & 3;
    const int wn   = wid >> 2;
    const int lr   = lane & 7;
    const int lg   = lane >> 3;
    const int h    = blockIdx.y;
    const int m0   = blockIdx.x * 128;
    const int z    = blockIdx.z;

    // ---- load Q tile, split to bf16 hi/lo ----
    const float* qbase = g_q + (h * M_TOK + m0) * D_HEAD;
    #pragma unroll
    for (int i = 0; i < 16; ++i) {
        int idx = t + i * 256;         // 0..4095 float4
        int row = idx >> 5;
        int c4  = idx & 31;
        float4 v = *(const float4*)(qbase + row * 128 + c4 * 4);
        __nv_bfloat16 h0, l0, h1, l1, h2, l2, h3, l3;
        split_bf16(v.x, h0, l0); split_bf16(v.y, h1, l1);
        split_bf16(v.z, h2, l2); split_bf16(v.w, h3, l3);
        *(uint2*)(sm + Q_HI_OFF + row * QP_B + c4 * 8) = make_uint2(pack2(h0, h1), pack2(h2, h3));
        *(uint2*)(sm + Q_LO_OFF + row * QP_B + c4 * 8) = make_uint2(pack2(l0, l1), pack2(l2, l3));
    }

    // PV accumulators: warp tile 32m x 64d -> 2 x 8 frags
    float out_acc[2][8][4];
    #pragma unroll
    for (int mi = 0; mi < 2; ++mi)
        #pragma unroll
        for (int nd = 0; nd < 8; ++nd)
            #pragma unroll
            for (int e = 0; e < 4; ++e) out_acc[mi][nd][e] = 0.f;
    float den = 0.f;

    for (int ch = 0; ch < 2048 / CL; ++ch) {
        const int l0 = z * 2048 + ch * CL;
        __syncthreads();   // prev PV done reading Ps/Vs; K free

        // ---- load K and V chunk, split to bf16 hi/lo ----
        #pragma unroll
        for (int i = 0; i < 8; ++i) {
            int idx = t + i * 256;       // 0..2047 float4
            int row = idx >> 5;          // 0..63
            int c4  = idx & 31;
            int lg_ = l0 + row;
            bool fresh = (lg_ >= P && lg_ < P + M_TOK);
            const float* srcK = fresh
                ? (g_k + (h * M_TOK + (lg_ - P)) * D_HEAD)
                : (cK + (h * L_CACHE + lg_) * D_HEAD);
            float4 v = *(const float4*)(srcK + c4 * 4);
            __nv_bfloat16 a0, b0, a1, b1, a2, b2, a3, b3;
            split_bf16(v.x, a0, b0); split_bf16(v.y, a1, b1);
            split_bf16(v.z, a2, b2); split_bf16(v.w, a3, b3);
            *(uint2*)(sm + K_HI_OFF + row * QP_B + c4 * 8) = make_uint2(pack2(a0, a1), pack2(a2, a3));
            *(uint2*)(sm + K_LO_OFF + row * QP_B + c4 * 8) = make_uint2(pack2(b0, b1), pack2(b2, b3));
            const float* srcV = fresh
                ? (g_v + (h * M_TOK + (lg_ - P)) * D_HEAD)
                : (cV + (h * L_CACHE + lg_) * D_HEAD);
            v = *(const float4*)(srcV + c4 * 4);
            split_bf16(v.x, a0, b0); split_bf16(v.y, a1, b1);
            split_bf16(v.z, a2, b2); split_bf16(v.w, a3, b3);
            *(uint2*)(sm + V_HI_OFF + row * QP_B + c4 * 8) = make_uint2(pack2(a0, a1), pack2(a2, a3));
            *(uint2*)(sm + V_LO_OFF + row * QP_B + c4 * 8) = make_uint2(pack2(b0, b1), pack2(b2, b3));
        }
        __syncthreads();

        // ---- S = Q K^T via mma.sync bf16x3 (warp tile 32m x 32l) ----
        float s[2][4][4];
        #pragma unroll
        for (int mi = 0; mi < 2; ++mi)
            #pragma unroll
            for (int nj = 0; nj < 4; ++nj)
                #pragma unroll
                for (int e = 0; e < 4; ++e) s[mi][nj][e] = 0.f;

        #pragma unroll
        for (int ks = 0; ks < 8; ++ks) {
            uint32_t aHi[2][4], aLo[2][4], bHi[4][2], bLo[4][2];
            #pragma unroll
            for (int mi = 0; mi < 2; ++mi) {
                int row = wm * 32 + mi * 16 + lr + (lg & 1) * 8;
                uint32_t ad = sb + Q_HI_OFF + row * QP_B + ks * 32 + (lg >> 1) * 16;
                ldm_x4(aHi[mi][0], aHi[mi][1], aHi[mi][2], aHi[mi][3], ad);
                ldm_x4(aLo[mi][0], aLo[mi][1], aLo[mi][2], aLo[mi][3], ad + Q_LO_OFF);
            }
            #pragma unroll
            for (int ng = 0; ng < 2; ++ng) {
                int row = wn * 32 + ng * 16 + (lg >> 1) * 8 + lr;
                uint32_t bd = sb + K_HI_OFF + row * QP_B + ks * 32 + (lg & 1) * 16;
                uint32_t d0, d1, d2, d3;
                ldm_x4(d0, d1, d2, d3, bd);
                bHi[ng * 2][0] = d0; bHi[ng * 2][1] = d1;
                bHi[ng * 2 + 1][0] = d2; bHi[ng * 2 + 1][1] = d3;
                ldm_x4(d0, d1, d2, d3, bd + (K_LO_OFF - K_HI_OFF));
                bLo[ng * 2][0] = d0; bLo[ng * 2][1] = d1;
                bLo[ng * 2 + 1][0] = d2; bLo[ng * 2 + 1][1] = d3;
            }
            #pragma unroll
            for (int mi = 0; mi < 2; ++mi)
                #pragma unroll
                for (int nj = 0; nj < 4; ++nj) {
                    mma16816(s[mi][nj], aHi[mi], bHi[nj]);
                    mma16816(s[mi][nj], aHi[mi], bLo[nj]);
                    mma16816(s[mi][nj], aLo[mi], bHi[nj]);
                }
        }

        // exp in registers
        #pragma unroll
        for (int mi = 0; mi < 2; ++mi)
            #pragma unroll
            for (int nj = 0; nj < 4; ++nj)
                #pragma unroll
                for (int e = 0; e < 4; ++e) s[mi][nj][e] = __expf(s[mi][nj][e]);

        // denominator: register shfl reduce over the warp's 32 l-columns
        #pragma unroll
        for (int mi = 0; mi < 2; ++mi) {
            float sa = 0.f, sbv = 0.f;
            #pragma unroll
            for (int nj = 0; nj < 4; ++nj) {
                sa  += s[mi][nj][0] + s[mi][nj][1];
                sbv += s[mi][nj][2] + s[mi][nj][3];
            }
            sa  += __shfl_xor_sync(0xffffffffu, sa, 1);
            sa  += __shfl_xor_sync(0xffffffffu, sa, 2);
            sbv += __shfl_xor_sync(0xffffffffu, sbv, 1);
            sbv += __shfl_xor_sync(0xffffffffu, sbv, 2);
            if ((lane & 3) == 0) {
                int row = wm * 32 + mi * 16 + (lane >> 2);
                denb[wn * 128 + row]     = sa;
                denb[wn * 128 + row + 8] = sbv;
            }
        }

        // store P split hi/lo to Ps (bf16, pitch 144B)
        {
            int r0 = wm * 32 + (lane >> 2);
            int c0 = wn * 32 + (lane & 3) * 2;
            #pragma unroll
            for (int mi = 0; mi < 2; ++mi)
                #pragma unroll
                for (int nj = 0; nj < 4; ++nj) {
                    int row = r0 + mi * 16;
                    int col = c0 + nj * 8;
                    __nv_bfloat16 h0, l0b, h1, l1b;
                    split_bf16(s[mi][nj][0], h0, l0b);
                    split_bf16(s[mi][nj][1], h1, l1b);
                    *(uint32_t*)(sm + PS_HI_OFF + row * PSP_B + col * 2) = pack2(h0, h1);
                    *(uint32_t*)(sm + PS_LO_OFF + row * PSP_B + col * 2) = pack2(l0b, l1b);
                    split_bf16(s[mi][nj][2], h0, l0b);
                    split_bf16(s[mi][nj][3], h1, l1b);
                    *(uint32_t*)(sm + PS_HI_OFF + (row + 8) * PSP_B + col * 2) = pack2(h0, h1);
                    *(uint32_t*)(sm + PS_LO_OFF + (row + 8) * PSP_B + col * 2) = pack2(l0b, l1b);
                }
        }
        __syncthreads();

        if (t < 128) den += denb[t] + denb[128 + t];

        // ---- out += P V via mma.sync bf16x3 (warp tile 32m x 64d) ----
        #pragma unroll
        for (int kp = 0; kp < 4; ++kp) {
            uint32_t aPhi[2][4], aPlo[2][4], bVhi[8][2], bVlo[8][2];
            #pragma unroll
            for (int mi = 0; mi < 2; ++mi) {
                int row = wm * 32 + mi * 16 + lr + (lg & 1) * 8;
                uint32_t ad = sb + PS_HI_OFF + row * PSP_B + kp * 32 + (lg >> 1) * 16;
                ldm_x4(aPhi[mi][0], aPhi[mi][1], aPhi[mi][2], aPhi[mi][3], ad);
                ldm_x4(aPlo[mi][0], aPlo[mi][1], aPlo[mi][2], aPlo[mi][3],
                       ad + (PS_LO_OFF - PS_HI_OFF));
            }
            #pragma unroll
            for (int ng = 0; ng < 4; ++ng) {   // each covers 16 d-cols = 2 n-frags
                int vrow = kp * 16 + (lg & 1) * 8 + lr;
                int vcol = wn * 64 + ng * 16 + (lg >> 1) * 8;
                uint32_t bd = sb + V_HI_OFF + vrow * QP_B + vcol * 2;
                uint32_t d0, d1, d2, d3;
                ldm_x4_t(d0, d1, d2, d3, bd);
                bVhi[ng * 2][0] = d0; bVhi[ng * 2][1] = d1;
                bVhi[ng * 2 + 1][0] = d2; bVhi[ng * 2 + 1][1] = d3;
                ldm_x4_t(d0, d1, d2, d3, bd + (V_LO_OFF - V_HI_OFF));
                bVlo[ng * 2][0] = d0; bVlo[ng * 2][1] = d1;
                bVlo[ng * 2 + 1][0] = d2; bVlo[ng * 2 + 1][1] = d3;
            }
            #pragma unroll
            for (int mi = 0; mi < 2; ++mi)
                #pragma unroll
                for (int nd = 0; nd < 8; ++nd) {
                    mma16816(out_acc[mi][nd], aPhi[mi], bVhi[nd]);
                    mma16816(out_acc[mi][nd], aPhi[mi], bVlo[nd]);
                    mma16816(out_acc[mi][nd], aPlo[mi], bVhi[nd]);
                }
        }
    }

    // write partial numerator / denominator
    float* po = g_po + ((size_t)(z * H_HEADS + h) * M_TOK + m0) * D_HEAD;
    #pragma unroll
    for (int mi = 0; mi < 2; ++mi)
        #pragma unroll
        for (int nd = 0; nd < 8; ++nd) {
            int row = wm * 32 + mi * 16 + (lane >> 2);
            int col = wn * 64 + nd * 8 + (lane & 3) * 2;
            *(float2*)(po + (size_t)row * D_HEAD + col) =
                make_float2(out_acc[mi][nd][0], out_acc[mi][nd][1]);
            *(float2*)(po + (size_t)(row + 8) * D_HEAD + col) =
                make_float2(out_acc[mi][nd][2], out_acc[mi][nd][3]);
        }
    if (t < 128)
        g_pd[(z * H_HEADS + h) * M_TOK + m0 + t] = den;
}

// ============================================================
// Kernel 4: combine L-splits and write output [M, H*D]
// ============================================================
__global__ __launch_bounds__(256) void combine_kernel(float* __restrict__ out)
{
    int idx = blockIdx.x * 256 + threadIdx.x;
    int e = idx * 4;
    int d = e & 127;
    int m = (e >> 7) & 511;
    int h = e >> 16;

    float4 a = *(const float4*)(g_po + e);
    float4 b = *(const float4*)(g_po + H_HEADS * M_TOK * D_HEAD + e);
    float dn = g_pd[h * M_TOK + m] + g_pd[H_HEADS * M_TOK + h * M_TOK + m];
    float inv = 1.0f / dn;
    float4 r = make_float4((a.x + b.x) * inv, (a.y + b.y) * inv,
                           (a.z + b.z) * inv, (a.w + b.w) * inv);
    *(float4*)(out + m * N_DIM + h * D_HEAD + d) = r;
}

// ============================================================
extern "C" void kernel_launch(void* const* d_in, const int* in_sizes, int n_in,
                              void* d_out, int out_size)
{
    const float* X  = (const float*)d_in[0];
    const float* W  = (const float*)d_in[1];
    const float* cK = (const float*)d_in[2];
    const float* cV = (const float*)d_in[3];
    const int*   Pp = (const int*)d_in[4];
    float* out = (float*)d_out;

    cudaFuncSetAttribute(attn_kernel,
                         cudaFuncAttributeMaxDynamicSharedMemorySize, ATTN_SMEM_B);
    cudaFuncSetAttribute(qkv_mma_kernel,
                         cudaFuncAttributeMaxDynamicSharedMemorySize, GEMM_SMEM);

    convert_x_kernel<<<(M_TOK * N_DIM / 4) / 256, 256>>>(X);
    convert_w_kernel<<<dim3(N3 / 32, N_DIM / 32), dim3(32, 8)>>>(W);
    qkv_mma_kernel<<<dim3(N3 / 64, M_TOK / 128), 256, GEMM_SMEM>>>();
    rmsnorm_kernel<<<dim3((H_HEADS * M_TOK) / 8, 2), 256>>>();
    attn_kernel<<<dim3(M_TOK / 128, H_HEADS, 2), 256, ATTN_SMEM_B>>>(cK, cV, Pp);
    combine_kernel<<<(H_HEADS * M_TOK * D_HEAD / 4) / 256, 256>>>(out);
}

// round 9
// speedup vs baseline: 3.3051x; 1.0173x over previous
#include <cuda_runtime.h>
#include <cuda_bf16.h>
#include <cstdint>

// Problem dims (fixed by dataset)
#define M_TOK   512
#define N_DIM   2048
#define D_HEAD  128
#define H_HEADS 16
#define L_CACHE 4096
#define N3      6144   // 3*N_DIM

// -------- device scratch (no allocations allowed) --------
__device__ float g_q[H_HEADS * M_TOK * D_HEAD];   // [H][M][D]
__device__ float g_k[H_HEADS * M_TOK * D_HEAD];
__device__ float g_v[H_HEADS * M_TOK * D_HEAD];
__device__ float g_po[2 * H_HEADS * M_TOK * D_HEAD]; // partial numerators per L-split
__device__ float g_pd[2 * H_HEADS * M_TOK];           // partial denominators

// bf16x3 split operands for warp-MMA QKV GEMM
__device__ __nv_bfloat16 g_xhi[M_TOK * N_DIM];        // X  [m][k]
__device__ __nv_bfloat16 g_xlo[M_TOK * N_DIM];
__device__ __nv_bfloat16 g_wthi[(size_t)N3 * N_DIM];  // W^T [n][k]
__device__ __nv_bfloat16 g_wtlo[(size_t)N3 * N_DIM];

// pre-split, scatter-updated KV cache [H][L][D]
__device__ __nv_bfloat16 g_kchi[(size_t)H_HEADS * L_CACHE * D_HEAD];
__device__ __nv_bfloat16 g_kclo[(size_t)H_HEADS * L_CACHE * D_HEAD];
__device__ __nv_bfloat16 g_vchi[(size_t)H_HEADS * L_CACHE * D_HEAD];
__device__ __nv_bfloat16 g_vclo[(size_t)H_HEADS * L_CACHE * D_HEAD];

// ============================================================
// helpers
// ============================================================
__device__ __forceinline__ uint32_t smem_u32(const void* p) {
    uint32_t a;
    asm("{ .reg .u64 t; cvta.to.shared.u64 t, %1; cvt.u32.u64 %0, t; }"
        : "=r"(a) : "l"(p));
    return a;
}

__device__ __forceinline__ void ldm_x4(uint32_t& d0, uint32_t& d1,
                                       uint32_t& d2, uint32_t& d3, uint32_t addr) {
    asm volatile("ldmatrix.sync.aligned.m8n8.x4.shared.b16 {%0,%1,%2,%3}, [%4];"
                 : "=r"(d0), "=r"(d1), "=r"(d2), "=r"(d3) : "r"(addr));
}

__device__ __forceinline__ void ldm_x4_t(uint32_t& d0, uint32_t& d1,
                                         uint32_t& d2, uint32_t& d3, uint32_t addr) {
    asm volatile("ldmatrix.sync.aligned.m8n8.x4.trans.shared.b16 {%0,%1,%2,%3}, [%4];"
                 : "=r"(d0), "=r"(d1), "=r"(d2), "=r"(d3) : "r"(addr));
}

__device__ __forceinline__ void mma16816(float* c, const uint32_t* a, const uint32_t* b) {
    asm volatile(
        "mma.sync.aligned.m16n8k16.row.col.f32.bf16.bf16.f32 "
        "{%0,%1,%2,%3}, {%4,%5,%6,%7}, {%8,%9}, {%0,%1,%2,%3};"
        : "+f"(c[0]), "+f"(c[1]), "+f"(c[2]), "+f"(c[3])
        : "r"(a[0]), "r"(a[1]), "r"(a[2]), "r"(a[3]), "r"(b[0]), "r"(b[1]));
}

__device__ __forceinline__ void split_bf16(float x, __nv_bfloat16& hi, __nv_bfloat16& lo) {
    hi = __float2bfloat16_rn(x);
    lo = __float2bfloat16_rn(x - __bfloat162float(hi));
}

__device__ __forceinline__ uint32_t pack2(__nv_bfloat16 a, __nv_bfloat16 b) {
    return (uint32_t)__bfloat16_as_ushort(a) | ((uint32_t)__bfloat16_as_ushort(b) << 16);
}

// ============================================================
// Kernel 0a: split X -> g_xhi/g_xlo  [m][k]
// ============================================================
__global__ __launch_bounds__(256) void convert_x_kernel(const float* __restrict__ X)
{
    int idx = blockIdx.x * 256 + threadIdx.x;      // float4 index
    float4 v = *(const float4*)(X + idx * 4);
    __nv_bfloat16 h0, l0, h1, l1, h2, l2, h3, l3;
    split_bf16(v.x, h0, l0); split_bf16(v.y, h1, l1);
    split_bf16(v.z, h2, l2); split_bf16(v.w, h3, l3);
    __nv_bfloat162* ph = (__nv_bfloat162*)(g_xhi + idx * 4);
    __nv_bfloat162* pl = (__nv_bfloat162*)(g_xlo + idx * 4);
    ph[0] = __nv_bfloat162(h0, h1); ph[1] = __nv_bfloat162(h2, h3);
    pl[0] = __nv_bfloat162(l0, l1); pl[1] = __nv_bfloat162(l2, l3);
}

// ============================================================
// Kernel 0b: transpose+split W[k][n] -> g_wthi/g_wtlo [n][k]
// ============================================================
__global__ __launch_bounds__(256) void convert_w_kernel(const float* __restrict__ W)
{
    __shared__ float tile[32][33];
    const int n0 = blockIdx.x * 32;
    const int k0 = blockIdx.y * 32;
    const int tx = threadIdx.x, ty = threadIdx.y;

    #pragma unroll
    for (int l = 0; l < 4; ++l)
        tile[ty * 4 + l][tx] = W[(size_t)(k0 + ty * 4 + l) * N3 + n0 + tx];
    __syncthreads();

    #pragma unroll
    for (int l = 0; l < 4; ++l) {
        int nl = ty * 4 + l;
        float x = tile[tx][nl];
        __nv_bfloat16 hi, lo;
        split_bf16(x, hi, lo);
        size_t o = (size_t)(n0 + nl) * N_DIM + k0 + tx;
        g_wthi[o] = hi;
        g_wtlo[o] = lo;
    }
}

// ============================================================
// Kernel 1: QKV GEMM via mma.sync bf16x3 (hi*hi + hi*lo + lo*hi)
// BM=128, BN=64, BK=32; 256 thr = 8 warps (4x2), warp tile 32x32.
// ============================================================
#define PITCH_B   80
#define A_TILE_B  (128 * PITCH_B)   // 10240
#define B_TILE_B  (64  * PITCH_B)   // 5120
#define OFF_AHI   0
#define OFF_ALO   A_TILE_B
#define OFF_BHI   (2 * A_TILE_B)
#define OFF_BLO   (2 * A_TILE_B + B_TILE_B)
#define BUF_B     (2 * A_TILE_B + 2 * B_TILE_B)   // 30720
#define GEMM_SMEM (2 * BUF_B)                     // 61440

__global__ __launch_bounds__(256) void qkv_mma_kernel()
{
    extern __shared__ __align__(128) char sm[];
    const uint32_t sb = smem_u32(sm);
    const int t    = threadIdx.x;
    const int lane = t & 31;
    const int wid  = t >> 5;
    const int wm   = wid & 3;        // 0..3  (m-warp)
    const int wn   = wid >> 2;       // 0..1  (n-warp)
    const int lg   = lane >> 3;      // ldmatrix group 0..3
    const int lr   = lane & 7;
    const int m0   = blockIdx.y * 128;
    const int n0   = blockIdx.x * 64;

    auto load_tiles = [&](int k0, int buf) {
        char* base = sm + buf * BUF_B;
        #pragma unroll
        for (int i = 0; i < 6; ++i) {
            int idx = t + i * 256;                 // 0..1535 16B chunks
            const __nv_bfloat16* gsrc;
            int local, off;
            if (idx < 512)       { gsrc = g_xhi  + (size_t)m0 * N_DIM; local = idx;        off = OFF_AHI; }
            else if (idx < 1024) { gsrc = g_xlo  + (size_t)m0 * N_DIM; local = idx - 512;  off = OFF_ALO; }
            else if (idx < 1280) { gsrc = g_wthi + (size_t)n0 * N_DIM; local = idx - 1024; off = OFF_BHI; }
            else                 { gsrc = g_wtlo + (size_t)n0 * N_DIM; local = idx - 1280; off = OFF_BLO; }
            int r = local >> 2, c = local & 3;
            uint4 v = *(const uint4*)(gsrc + (size_t)r * N_DIM + k0 + c * 8);
            *(uint4*)(base + off + r * PITCH_B + c * 16) = v;
        }
    };

    float acc[2][4][4];
    #pragma unroll
    for (int mi = 0; mi < 2; ++mi)
        #pragma unroll
        for (int nf = 0; nf < 4; ++nf)
            #pragma unroll
            for (int e = 0; e < 4; ++e) acc[mi][nf][e] = 0.f;

    load_tiles(0, 0);

    const int NIT = N_DIM / 32;    // 64
    for (int it = 0; it < NIT; ++it) {
        const int buf = it & 1;
        __syncthreads();
        if (it + 1 < NIT) load_tiles((it + 1) * 32, buf ^ 1);

        const uint32_t bb = sb + buf * BUF_B;
        #pragma unroll
        for (int ks = 0; ks < 2; ++ks) {
            uint32_t aHi[2][4], aLo[2][4], bHi[4][2], bLo[4][2];
            #pragma unroll
            for (int mi = 0; mi < 2; ++mi) {
                int row = wm * 32 + mi * 16 + lr + (lg & 1) * 8;
                int col = ks * 16 + (lg >> 1) * 8;
                uint32_t ad = bb + OFF_AHI + row * PITCH_B + col * 2;
                ldm_x4(aHi[mi][0], aHi[mi][1], aHi[mi][2], aHi[mi][3], ad);
                ldm_x4(aLo[mi][0], aLo[mi][1], aLo[mi][2], aLo[mi][3], ad + (OFF_ALO - OFF_AHI));
            }
            #pragma unroll
            for (int nj = 0; nj < 2; ++nj) {
                int row = wn * 32 + nj * 16 + (lg >> 1) * 8 + lr;
                int col = ks * 16 + (lg & 1) * 8;
                uint32_t bd = bb + OFF_BHI + row * PITCH_B + col * 2;
                uint32_t d0, d1, d2, d3;
                ldm_x4(d0, d1, d2, d3, bd);
                bHi[nj * 2][0] = d0; bHi[nj * 2][1] = d1;
                bHi[nj * 2 + 1][0] = d2; bHi[nj * 2 + 1][1] = d3;
                ldm_x4(d0, d1, d2, d3, bd + (OFF_BLO - OFF_BHI));
                bLo[nj * 2][0] = d0; bLo[nj * 2][1] = d1;
                bLo[nj * 2 + 1][0] = d2; bLo[nj * 2 + 1][1] = d3;
            }
            #pragma unroll
            for (int mi = 0; mi < 2; ++mi)
                #pragma unroll
                for (int nf = 0; nf < 4; ++nf) {
                    mma16816(acc[mi][nf], aHi[mi], bHi[nf]);
                    mma16816(acc[mi][nf], aHi[mi], bLo[nf]);
                    mma16816(acc[mi][nf], aLo[mi], bHi[nf]);
                }
        }
    }

    const int part  = n0 >> 11;
    const int h     = (n0 >> 7) & 15;
    const int dbase = n0 & 64;
    float* dstp = (part == 0 ? g_q : (part == 1 ? g_k : g_v))
                  + (size_t)h * (M_TOK * D_HEAD);

    #pragma unroll
    for (int mi = 0; mi < 2; ++mi)
        #pragma unroll
        for (int nf = 0; nf < 4; ++nf) {
            int row = m0 + wm * 32 + mi * 16 + (lane >> 2);
            int col = dbase + wn * 32 + nf * 8 + (lane & 3) * 2;
            *(float2*)(dstp + (size_t)row * D_HEAD + col) =
                make_float2(acc[mi][nf][0], acc[mi][nf][1]);
            *(float2*)(dstp + (size_t)(row + 8) * D_HEAD + col) =
                make_float2(acc[mi][nf][2], acc[mi][nf][3]);
        }
}

// ============================================================
// Kernel 2: RMS norm rows of g_q and g_k (warp per row)
// ============================================================
__global__ __launch_bounds__(256) void rmsnorm_kernel()
{
    const int warp = threadIdx.x >> 5;
    const int lane = threadIdx.x & 31;
    const int row  = blockIdx.x * 8 + warp;
    float* base = (blockIdx.y == 0 ? g_q : g_k) + row * D_HEAD;

    float4 v = *(float4*)(base + lane * 4);
    float ss = v.x * v.x + v.y * v.y + v.z * v.z + v.w * v.w;
    #pragma unroll
    for (int off = 16; off > 0; off >>= 1)
        ss += __shfl_xor_sync(0xffffffffu, ss, off);
    float s = rsqrtf(ss * (1.0f / 128.0f));
    v.x *= s; v.y *= s; v.z *= s; v.w *= s;
    *(float4*)(base + lane * 4) = v;
}

// ============================================================
// Kernel 2b: build pre-split scatter-updated KV cache
// g_kchi/lo, g_vchi/lo [H][L][D] from cache + fresh g_k/g_v.
// ============================================================
__global__ __launch_bounds__(256) void convert_kv_kernel(
    const float* __restrict__ cK, const float* __restrict__ cV,
    const int* __restrict__ Pp)
{
    const int P = Pp[0];
    int idx = blockIdx.x * 256 + threadIdx.x;      // float4 index over H*L*D
    int e = idx * 4;
    int d = e & 127;
    int l = (e >> 7) & (L_CACHE - 1);
    int h = e >> 19;                               // 128*4096 = 2^19
    size_t o = (size_t)h * (L_CACHE * D_HEAD) + (size_t)l * D_HEAD + d;
    bool fresh = (l >= P && l < P + M_TOK);
    size_t of = ((size_t)h * M_TOK + (l - P)) * D_HEAD + d;

    float4 kv = fresh ? *(const float4*)(g_k + of) : *(const float4*)(cK + o);
    __nv_bfloat16 a0, b0, a1, b1, a2, b2, a3, b3;
    split_bf16(kv.x, a0, b0); split_bf16(kv.y, a1, b1);
    split_bf16(kv.z, a2, b2); split_bf16(kv.w, a3, b3);
    *(uint2*)(g_kchi + o) = make_uint2(pack2(a0, a1), pack2(a2, a3));
    *(uint2*)(g_kclo + o) = make_uint2(pack2(b0, b1), pack2(b2, b3));

    kv = fresh ? *(const float4*)(g_v + of) : *(const float4*)(cV + o);
    split_bf16(kv.x, a0, b0); split_bf16(kv.y, a1, b1);
    split_bf16(kv.z, a2, b2); split_bf16(kv.w, a3, b3);
    *(uint2*)(g_vchi + o) = make_uint2(pack2(a0, a1), pack2(a2, a3));
    *(uint2*)(g_vclo + o) = make_uint2(pack2(b0, b1), pack2(b2, b3));
}

// ============================================================
// Kernel 3: full-tensor attention.
//   S = Q K^T  via mma.sync bf16x3 (pre-split K from global)
//   exp in registers; P split hi/lo -> smem bf16
//   out += P V via mma.sync bf16x3 (pre-split V, ldmatrix.trans)
// grid (4, 16, 2), 256 thr = 8 warps (4m x 2n), chunk CL=64.
// ============================================================
#define CL        64
#define QP_B      272                        // 128 bf16 + 8 pad
#define PSP_B     144                        // 64 bf16 + 8 pad
#define Q_HI_OFF  0
#define Q_LO_OFF  (128 * QP_B)               // 34816
#define K_HI_OFF  (2 * 128 * QP_B)           // 69632
#define K_LO_OFF  (K_HI_OFF + CL * QP_B)     // 87040
#define V_HI_OFF  (K_LO_OFF + CL * QP_B)     // 104448
#define V_LO_OFF  (V_HI_OFF + CL * QP_B)     // 121856
#define PS_HI_OFF (V_LO_OFF + CL * QP_B)     // 139264
#define PS_LO_OFF (PS_HI_OFF + 128 * PSP_B)  // 157696
#define DEN_OFF   (PS_LO_OFF + 128 * PSP_B)  // 176128
#define ATTN_SMEM_B (DEN_OFF + 2 * 128 * 4)  // 177152

__global__ __launch_bounds__(256, 1) void attn_kernel()
{
    extern __shared__ __align__(128) char sm[];
    const uint32_t sb = smem_u32(sm);
    float* denb = (float*)(sm + DEN_OFF);   // [2][128]

    const int t    = threadIdx.x;
    const int lane = t & 31;
    const int wid  = t >> 5;
    const int wm   = wid & 3;
    const int wn   = wid >> 2;
    const int lr   = lane & 7;
    const int lg   = lane >> 3;
    const int h    = blockIdx.y;
    const int m0   = blockIdx.x * 128;
    const int z    = blockIdx.z;

    // ---- load Q tile, split to bf16 hi/lo ----
    const float* qbase = g_q + (h * M_TOK + m0) * D_HEAD;
    #pragma unroll
    for (int i = 0; i < 16; ++i) {
        int idx = t + i * 256;         // 0..4095 float4
        int row = idx >> 5;
        int c4  = idx & 31;
        float4 v = *(const float4*)(qbase + row * 128 + c4 * 4);
        __nv_bfloat16 h0, l0, h1, l1, h2, l2, h3, l3;
        split_bf16(v.x, h0, l0); split_bf16(v.y, h1, l1);
        split_bf16(v.z, h2, l2); split_bf16(v.w, h3, l3);
        *(uint2*)(sm + Q_HI_OFF + row * QP_B + c4 * 8) = make_uint2(pack2(h0, h1), pack2(h2, h3));
        *(uint2*)(sm + Q_LO_OFF + row * QP_B + c4 * 8) = make_uint2(pack2(l0, l1), pack2(l2, l3));
    }

    // PV accumulators: warp tile 32m x 64d -> 2 x 8 frags
    float out_acc[2][8][4];
    #pragma unroll
    for (int mi = 0; mi < 2; ++mi)
        #pragma unroll
        for (int nd = 0; nd < 8; ++nd)
            #pragma unroll
            for (int e = 0; e < 4; ++e) out_acc[mi][nd][e] = 0.f;
    float den = 0.f;

    const size_t hoff = (size_t)h * (L_CACHE * D_HEAD);

    for (int ch = 0; ch < 2048 / CL; ++ch) {
        const int l0 = z * 2048 + ch * CL;
        __syncthreads();   // prev phase done reading Ps/Vs/K

        // ---- load pre-split K/V chunk: straight LDG.128 -> STS.128 ----
        {
            const char* srcs[4] = {
                (const char*)(g_kchi + hoff + (size_t)l0 * D_HEAD),
                (const char*)(g_kclo + hoff + (size_t)l0 * D_HEAD),
                (const char*)(g_vchi + hoff + (size_t)l0 * D_HEAD),
                (const char*)(g_vclo + hoff + (size_t)l0 * D_HEAD)
            };
            const uint32_t dsts[4] = {K_HI_OFF, K_LO_OFF, V_HI_OFF, V_LO_OFF};
            #pragma unroll
            for (int i = 0; i < 16; ++i) {
                int idx   = t + i * 256;      // 0..4095 16B chunks
                int a     = i >> 2;           // array 0..3 (i*256 spans 1024 per array)
                int local = idx & 1023;
                int row   = local >> 4;       // 0..63
                int c     = local & 15;       // 16B chunk in 256B row
                uint4 v = *(const uint4*)(srcs[a] + row * 256 + c * 16);
                *(uint4*)(sm + dsts[a] + row * QP_B + c * 16) = v;
            }
        }
        __syncthreads();

        // ---- S = Q K^T via mma.sync bf16x3 (warp tile 32m x 32l) ----
        float s[2][4][4];
        #pragma unroll
        for (int mi = 0; mi < 2; ++mi)
            #pragma unroll
            for (int nj = 0; nj < 4; ++nj)
                #pragma unroll
                for (int e = 0; e < 4; ++e) s[mi][nj][e] = 0.f;

        #pragma unroll
        for (int ks = 0; ks < 8; ++ks) {
            uint32_t aHi[2][4], aLo[2][4], bHi[4][2], bLo[4][2];
            #pragma unroll
            for (int mi = 0; mi < 2; ++mi) {
                int row = wm * 32 + mi * 16 + lr + (lg & 1) * 8;
                uint32_t ad = sb + Q_HI_OFF + row * QP_B + ks * 32 + (lg >> 1) * 16;
                ldm_x4(aHi[mi][0], aHi[mi][1], aHi[mi][2], aHi[mi][3], ad);
                ldm_x4(aLo[mi][0], aLo[mi][1], aLo[mi][2], aLo[mi][3], ad + Q_LO_OFF);
            }
            #pragma unroll
            for (int ng = 0; ng < 2; ++ng) {
                int row = wn * 32 + ng * 16 + (lg >> 1) * 8 + lr;
                uint32_t bd = sb + K_HI_OFF + row * QP_B + ks * 32 + (lg & 1) * 16;
                uint32_t d0, d1, d2, d3;
                ldm_x4(d0, d1, d2, d3, bd);
                bHi[ng * 2][0] = d0; bHi[ng * 2][1] = d1;
                bHi[ng * 2 + 1][0] = d2; bHi[ng * 2 + 1][1] = d3;
                ldm_x4(d0, d1, d2, d3, bd + (K_LO_OFF - K_HI_OFF));
                bLo[ng * 2][0] = d0; bLo[ng * 2][1] = d1;
                bLo[ng * 2 + 1][0] = d2; bLo[ng * 2 + 1][1] = d3;
            }
            #pragma unroll
            for (int mi = 0; mi < 2; ++mi)
                #pragma unroll
                for (int nj = 0; nj < 4; ++nj) {
                    mma16816(s[mi][nj], aHi[mi], bHi[nj]);
                    mma16816(s[mi][nj], aHi[mi], bLo[nj]);
                    mma16816(s[mi][nj], aLo[mi], bHi[nj]);
                }
        }

        // exp in registers
        #pragma unroll
        for (int mi = 0; mi < 2; ++mi)
            #pragma unroll
            for (int nj = 0; nj < 4; ++nj)
                #pragma unroll
                for (int e = 0; e < 4; ++e) s[mi][nj][e] = __expf(s[mi][nj][e]);

        // denominator: register shfl reduce over the warp's 32 l-columns
        #pragma unroll
        for (int mi = 0; mi < 2; ++mi) {
            float sa = 0.f, sbv = 0.f;
            #pragma unroll
            for (int nj = 0; nj < 4; ++nj) {
                sa  += s[mi][nj][0] + s[mi][nj][1];
                sbv += s[mi][nj][2] + s[mi][nj][3];
            }
            sa  += __shfl_xor_sync(0xffffffffu, sa, 1);
            sa  += __shfl_xor_sync(0xffffffffu, sa, 2);
            sbv += __shfl_xor_sync(0xffffffffu, sbv, 1);
            sbv += __shfl_xor_sync(0xffffffffu, sbv, 2);
            if ((lane & 3) == 0) {
                int row = wm * 32 + mi * 16 + (lane >> 2);
                denb[wn * 128 + row]     = sa;
                denb[wn * 128 + row + 8] = sbv;
            }
        }

        // store P split hi/lo to Ps (bf16, pitch 144B)
        {
            int r0 = wm * 32 + (lane >> 2);
            int c0 = wn * 32 + (lane & 3) * 2;
            #pragma unroll
            for (int mi = 0; mi < 2; ++mi)
                #pragma unroll
                for (int nj = 0; nj < 4; ++nj) {
                    int row = r0 + mi * 16;
                    int col = c0 + nj * 8;
                    __nv_bfloat16 h0, l0b, h1, l1b;
                    split_bf16(s[mi][nj][0], h0, l0b);
                    split_bf16(s[mi][nj][1], h1, l1b);
                    *(uint32_t*)(sm + PS_HI_OFF + row * PSP_B + col * 2) = pack2(h0, h1);
                    *(uint32_t*)(sm + PS_LO_OFF + row * PSP_B + col * 2) = pack2(l0b, l1b);
                    split_bf16(s[mi][nj][2], h0, l0b);
                    split_bf16(s[mi][nj][3], h1, l1b);
                    *(uint32_t*)(sm + PS_HI_OFF + (row + 8) * PSP_B + col * 2) = pack2(h0, h1);
                    *(uint32_t*)(sm + PS_LO_OFF + (row + 8) * PSP_B + col * 2) = pack2(l0b, l1b);
                }
        }
        __syncthreads();

        if (t < 128) den += denb[t] + denb[128 + t];

        // ---- out += P V via mma.sync bf16x3 (warp tile 32m x 64d) ----
        #pragma unroll
        for (int kp = 0; kp < 4; ++kp) {
            uint32_t aPhi[2][4], aPlo[2][4], bVhi[8][2], bVlo[8][2];
            #pragma unroll
            for (int mi = 0; mi < 2; ++mi) {
                int row = wm * 32 + mi * 16 + lr + (lg & 1) * 8;
                uint32_t ad = sb + PS_HI_OFF + row * PSP_B + kp * 32 + (lg >> 1) * 16;
                ldm_x4(aPhi[mi][0], aPhi[mi][1], aPhi[mi][2], aPhi[mi][3], ad);
                ldm_x4(aPlo[mi][0], aPlo[mi][1], aPlo[mi][2], aPlo[mi][3],
                       ad + (PS_LO_OFF - PS_HI_OFF));
            }
            #pragma unroll
            for (int ng = 0; ng < 4; ++ng) {   // each covers 16 d-cols = 2 n-frags
                int vrow = kp * 16 + (lg & 1) * 8 + lr;
                int vcol = wn * 64 + ng * 16 + (lg >> 1) * 8;
                uint32_t bd = sb + V_HI_OFF + vrow * QP_B + vcol * 2;
                uint32_t d0, d1, d2, d3;
                ldm_x4_t(d0, d1, d2, d3, bd);
                bVhi[ng * 2][0] = d0; bVhi[ng * 2][1] = d1;
                bVhi[ng * 2 + 1][0] = d2; bVhi[ng * 2 + 1][1] = d3;
                ldm_x4_t(d0, d1, d2, d3, bd + (V_LO_OFF - V_HI_OFF));
                bVlo[ng * 2][0] = d0; bVlo[ng * 2][1] = d1;
                bVlo[ng * 2 + 1][0] = d2; bVlo[ng * 2 + 1][1] = d3;
            }
            #pragma unroll
            for (int mi = 0; mi < 2; ++mi)
                #pragma unroll
                for (int nd = 0; nd < 8; ++nd) {
                    mma16816(out_acc[mi][nd], aPhi[mi], bVhi[nd]);
                    mma16816(out_acc[mi][nd], aPhi[mi], bVlo[nd]);
                    mma16816(out_acc[mi][nd], aPlo[mi], bVhi[nd]);
                }
        }
    }

    // write partial numerator / denominator
    float* po = g_po + ((size_t)(z * H_HEADS + h) * M_TOK + m0) * D_HEAD;
    #pragma unroll
    for (int mi = 0; mi < 2; ++mi)
        #pragma unroll
        for (int nd = 0; nd < 8; ++nd) {
            int row = wm * 32 + mi * 16 + (lane >> 2);
            int col = wn * 64 + nd * 8 + (lane & 3) * 2;
            *(float2*)(po + (size_t)row * D_HEAD + col) =
                make_float2(out_acc[mi][nd][0], out_acc[mi][nd][1]);
            *(float2*)(po + (size_t)(row + 8) * D_HEAD + col) =
                make_float2(out_acc[mi][nd][2], out_acc[mi][nd][3]);
        }
    if (t < 128)
        g_pd[(z * H_HEADS + h) * M_TOK + m0 + t] = den;
}

// ============================================================
// Kernel 4: combine L-splits and write output [M, H*D]
// ============================================================
__global__ __launch_bounds__(256) void combine_kernel(float* __restrict__ out)
{
    int idx = blockIdx.x * 256 + threadIdx.x;
    int e = idx * 4;
    int d = e & 127;
    int m = (e >> 7) & 511;
    int h = e >> 16;

    float4 a = *(const float4*)(g_po + e);
    float4 b = *(const float4*)(g_po + H_HEADS * M_TOK * D_HEAD + e);
    float dn = g_pd[h * M_TOK + m] + g_pd[H_HEADS * M_TOK + h * M_TOK + m];
    float inv = 1.0f / dn;
    float4 r = make_float4((a.x + b.x) * inv, (a.y + b.y) * inv,
                           (a.z + b.z) * inv, (a.w + b.w) * inv);
    *(float4*)(out + m * N_DIM + h * D_HEAD + d) = r;
}

// ============================================================
extern "C" void kernel_launch(void* const* d_in, const int* in_sizes, int n_in,
                              void* d_out, int out_size)
{
    const float* X  = (const float*)d_in[0];
    const float* W  = (const float*)d_in[1];
    const float* cK = (const float*)d_in[2];
    const float* cV = (const float*)d_in[3];
    const int*   Pp = (const int*)d_in[4];
    float* out = (float*)d_out;

    cudaFuncSetAttribute(attn_kernel,
                         cudaFuncAttributeMaxDynamicSharedMemorySize, ATTN_SMEM_B);
    cudaFuncSetAttribute(qkv_mma_kernel,
                         cudaFuncAttributeMaxDynamicSharedMemorySize, GEMM_SMEM);

    convert_x_kernel<<<(M_TOK * N_DIM / 4) / 256, 256>>>(X);
    convert_w_kernel<<<dim3(N3 / 32, N_DIM / 32), dim3(32, 8)>>>(W);
    qkv_mma_kernel<<<dim3(N3 / 64, M_TOK / 128), 256, GEMM_SMEM>>>();
    rmsnorm_kernel<<<dim3((H_HEADS * M_TOK) / 8, 2), 256>>>();
    convert_kv_kernel<<<(H_HEADS * L_CACHE * D_HEAD / 4) / 256, 256>>>(cK, cV, Pp);
    attn_kernel<<<dim3(M_TOK / 128, H_HEADS, 2), 256, ATTN_SMEM_B>>>();
    combine_kernel<<<(H_HEADS * M_TOK * D_HEAD / 4) / 256, 256>>>(out);
}

// round 10
// speedup vs baseline: 3.6131x; 1.0932x over previous
#include <cuda_runtime.h>
#include <cuda_bf16.h>
#include <cstdint>

// Problem dims (fixed by dataset)
#define M_TOK   512
#define N_DIM   2048
#define D_HEAD  128
#define H_HEADS 16
#define L_CACHE 4096
#define N3      6144   // 3*N_DIM

// -------- device scratch (no allocations allowed) --------
__device__ float g_q[H_HEADS * M_TOK * D_HEAD];   // [H][M][D]
__device__ float g_k[H_HEADS * M_TOK * D_HEAD];
__device__ float g_v[H_HEADS * M_TOK * D_HEAD];
__device__ float g_po[2 * H_HEADS * M_TOK * D_HEAD]; // partial numerators per L-split
__device__ float g_pd[2 * H_HEADS * M_TOK];           // partial denominators

// bf16x3 split operands for warp-MMA QKV GEMM
__device__ __nv_bfloat16 g_xhi[M_TOK * N_DIM];        // X  [m][k]
__device__ __nv_bfloat16 g_xlo[M_TOK * N_DIM];
__device__ __nv_bfloat16 g_wthi[(size_t)N3 * N_DIM];  // W^T [n][k]
__device__ __nv_bfloat16 g_wtlo[(size_t)N3 * N_DIM];

// pre-split, scatter-updated KV cache [H][L][D]
__device__ __nv_bfloat16 g_kchi[(size_t)H_HEADS * L_CACHE * D_HEAD];
__device__ __nv_bfloat16 g_kclo[(size_t)H_HEADS * L_CACHE * D_HEAD];
__device__ __nv_bfloat16 g_vchi[(size_t)H_HEADS * L_CACHE * D_HEAD];
__device__ __nv_bfloat16 g_vclo[(size_t)H_HEADS * L_CACHE * D_HEAD];

// ============================================================
// helpers
// ============================================================
__device__ __forceinline__ uint32_t smem_u32(const void* p) {
    uint32_t a;
    asm("{ .reg .u64 t; cvta.to.shared.u64 t, %1; cvt.u32.u64 %0, t; }"
        : "=r"(a) : "l"(p));
    return a;
}

__device__ __forceinline__ void ldm_x4(uint32_t& d0, uint32_t& d1,
                                       uint32_t& d2, uint32_t& d3, uint32_t addr) {
    asm volatile("ldmatrix.sync.aligned.m8n8.x4.shared.b16 {%0,%1,%2,%3}, [%4];"
                 : "=r"(d0), "=r"(d1), "=r"(d2), "=r"(d3) : "r"(addr));
}

__device__ __forceinline__ void ldm_x4_t(uint32_t& d0, uint32_t& d1,
                                         uint32_t& d2, uint32_t& d3, uint32_t addr) {
    asm volatile("ldmatrix.sync.aligned.m8n8.x4.trans.shared.b16 {%0,%1,%2,%3}, [%4];"
                 : "=r"(d0), "=r"(d1), "=r"(d2), "=r"(d3) : "r"(addr));
}

__device__ __forceinline__ void mma16816(float* c, const uint32_t* a, const uint32_t* b) {
    asm volatile(
        "mma.sync.aligned.m16n8k16.row.col.f32.bf16.bf16.f32 "
        "{%0,%1,%2,%3}, {%4,%5,%6,%7}, {%8,%9}, {%0,%1,%2,%3};"
        : "+f"(c[0]), "+f"(c[1]), "+f"(c[2]), "+f"(c[3])
        : "r"(a[0]), "r"(a[1]), "r"(a[2]), "r"(a[3]), "r"(b[0]), "r"(b[1]));
}

__device__ __forceinline__ void cp_async16(uint32_t dst, const void* src) {
    asm volatile("cp.async.cg.shared.global [%0], [%1], 16;" :: "r"(dst), "l"(src));
}
#define CP_COMMIT() asm volatile("cp.async.commit_group;" ::: "memory")
#define CP_WAIT0()  asm volatile("cp.async.wait_group 0;" ::: "memory")

__device__ __forceinline__ void split_bf16(float x, __nv_bfloat16& hi, __nv_bfloat16& lo) {
    hi = __float2bfloat16_rn(x);
    lo = __float2bfloat16_rn(x - __bfloat162float(hi));
}

__device__ __forceinline__ uint32_t pack2(__nv_bfloat16 a, __nv_bfloat16 b) {
    return (uint32_t)__bfloat16_as_ushort(a) | ((uint32_t)__bfloat16_as_ushort(b) << 16);
}

// ============================================================
// Kernel 0a: split X -> g_xhi/g_xlo  [m][k]
// ============================================================
__global__ __launch_bounds__(256) void convert_x_kernel(const float* __restrict__ X)
{
    int idx = blockIdx.x * 256 + threadIdx.x;      // float4 index
    float4 v = *(const float4*)(X + idx * 4);
    __nv_bfloat16 h0, l0, h1, l1, h2, l2, h3, l3;
    split_bf16(v.x, h0, l0); split_bf16(v.y, h1, l1);
    split_bf16(v.z, h2, l2); split_bf16(v.w, h3, l3);
    __nv_bfloat162* ph = (__nv_bfloat162*)(g_xhi + idx * 4);
    __nv_bfloat162* pl = (__nv_bfloat162*)(g_xlo + idx * 4);
    ph[0] = __nv_bfloat162(h0, h1); ph[1] = __nv_bfloat162(h2, h3);
    pl[0] = __nv_bfloat162(l0, l1); pl[1] = __nv_bfloat162(l2, l3);
}

// ============================================================
// Kernel 0b: transpose+split W[k][n] -> g_wthi/g_wtlo [n][k]
// ============================================================
__global__ __launch_bounds__(256) void convert_w_kernel(const float* __restrict__ W)
{
    __shared__ float tile[32][33];
    const int n0 = blockIdx.x * 32;
    const int k0 = blockIdx.y * 32;
    const int tx = threadIdx.x, ty = threadIdx.y;

    #pragma unroll
    for (int l = 0; l < 4; ++l)
        tile[ty * 4 + l][tx] = W[(size_t)(k0 + ty * 4 + l) * N3 + n0 + tx];
    __syncthreads();

    #pragma unroll
    for (int l = 0; l < 4; ++l) {
        int nl = ty * 4 + l;
        float x = tile[tx][nl];
        __nv_bfloat16 hi, lo;
        split_bf16(x, hi, lo);
        size_t o = (size_t)(n0 + nl) * N_DIM + k0 + tx;
        g_wthi[o] = hi;
        g_wtlo[o] = lo;
    }
}

// ============================================================
// Kernel 1: QKV GEMM via mma.sync bf16x3 (hi*hi + hi*lo + lo*hi)
// BM=128, BN=64, BK=32; 256 thr = 8 warps (4x2), warp tile 32x32.
// ============================================================
#define PITCH_B   80
#define A_TILE_B  (128 * PITCH_B)   // 10240
#define B_TILE_B  (64  * PITCH_B)   // 5120
#define OFF_AHI   0
#define OFF_ALO   A_TILE_B
#define OFF_BHI   (2 * A_TILE_B)
#define OFF_BLO   (2 * A_TILE_B + B_TILE_B)
#define BUF_B     (2 * A_TILE_B + 2 * B_TILE_B)   // 30720
#define GEMM_SMEM (2 * BUF_B)                     // 61440

__global__ __launch_bounds__(256) void qkv_mma_kernel()
{
    extern __shared__ __align__(128) char sm[];
    const uint32_t sb = smem_u32(sm);
    const int t    = threadIdx.x;
    const int lane = t & 31;
    const int wid  = t >> 5;
    const int wm   = wid & 3;        // 0..3  (m-warp)
    const int wn   = wid >> 2;       // 0..1  (n-warp)
    const int lg   = lane >> 3;      // ldmatrix group 0..3
    const int lr   = lane & 7;
    const int m0   = blockIdx.y * 128;
    const int n0   = blockIdx.x * 64;

    auto load_tiles = [&](int k0, int buf) {
        char* base = sm + buf * BUF_B;
        #pragma unroll
        for (int i = 0; i < 6; ++i) {
            int idx = t + i * 256;                 // 0..1535 16B chunks
            const __nv_bfloat16* gsrc;
            int local, off;
            if (idx < 512)       { gsrc = g_xhi  + (size_t)m0 * N_DIM; local = idx;        off = OFF_AHI; }
            else if (idx < 1024) { gsrc = g_xlo  + (size_t)m0 * N_DIM; local = idx - 512;  off = OFF_ALO; }
            else if (idx < 1280) { gsrc = g_wthi + (size_t)n0 * N_DIM; local = idx - 1024; off = OFF_BHI; }
            else                 { gsrc = g_wtlo + (size_t)n0 * N_DIM; local = idx - 1280; off = OFF_BLO; }
            int r = local >> 2, c = local & 3;
            uint4 v = *(const uint4*)(gsrc + (size_t)r * N_DIM + k0 + c * 8);
            *(uint4*)(base + off + r * PITCH_B + c * 16) = v;
        }
    };

    float acc[2][4][4];
    #pragma unroll
    for (int mi = 0; mi < 2; ++mi)
        #pragma unroll
        for (int nf = 0; nf < 4; ++nf)
            #pragma unroll
            for (int e = 0; e < 4; ++e) acc[mi][nf][e] = 0.f;

    load_tiles(0, 0);

    const int NIT = N_DIM / 32;    // 64
    for (int it = 0; it < NIT; ++it) {
        const int buf = it & 1;
        __syncthreads();
        if (it + 1 < NIT) load_tiles((it + 1) * 32, buf ^ 1);

        const uint32_t bb = sb + buf * BUF_B;
        #pragma unroll
        for (int ks = 0; ks < 2; ++ks) {
            uint32_t aHi[2][4], aLo[2][4], bHi[4][2], bLo[4][2];
            #pragma unroll
            for (int mi = 0; mi < 2; ++mi) {
                int row = wm * 32 + mi * 16 + lr + (lg & 1) * 8;
                int col = ks * 16 + (lg >> 1) * 8;
                uint32_t ad = bb + OFF_AHI + row * PITCH_B + col * 2;
                ldm_x4(aHi[mi][0], aHi[mi][1], aHi[mi][2], aHi[mi][3], ad);
                ldm_x4(aLo[mi][0], aLo[mi][1], aLo[mi][2], aLo[mi][3], ad + (OFF_ALO - OFF_AHI));
            }
            #pragma unroll
            for (int nj = 0; nj < 2; ++nj) {
                int row = wn * 32 + nj * 16 + (lg >> 1) * 8 + lr;
                int col = ks * 16 + (lg & 1) * 8;
                uint32_t bd = bb + OFF_BHI + row * PITCH_B + col * 2;
                uint32_t d0, d1, d2, d3;
                ldm_x4(d0, d1, d2, d3, bd);
                bHi[nj * 2][0] = d0; bHi[nj * 2][1] = d1;
                bHi[nj * 2 + 1][0] = d2; bHi[nj * 2 + 1][1] = d3;
                ldm_x4(d0, d1, d2, d3, bd + (OFF_BLO - OFF_BHI));
                bLo[nj * 2][0] = d0; bLo[nj * 2][1] = d1;
                bLo[nj * 2 + 1][0] = d2; bLo[nj * 2 + 1][1] = d3;
            }
            #pragma unroll
            for (int mi = 0; mi < 2; ++mi)
                #pragma unroll
                for (int nf = 0; nf < 4; ++nf) {
                    mma16816(acc[mi][nf], aHi[mi], bHi[nf]);
                    mma16816(acc[mi][nf], aHi[mi], bLo[nf]);
                    mma16816(acc[mi][nf], aLo[mi], bHi[nf]);
                }
        }
    }

    const int part  = n0 >> 11;
    const int h     = (n0 >> 7) & 15;
    const int dbase = n0 & 64;
    float* dstp = (part == 0 ? g_q : (part == 1 ? g_k : g_v))
                  + (size_t)h * (M_TOK * D_HEAD);

    #pragma unroll
    for (int mi = 0; mi < 2; ++mi)
        #pragma unroll
        for (int nf = 0; nf < 4; ++nf) {
            int row = m0 + wm * 32 + mi * 16 + (lane >> 2);
            int col = dbase + wn * 32 + nf * 8 + (lane & 3) * 2;
            *(float2*)(dstp + (size_t)row * D_HEAD + col) =
                make_float2(acc[mi][nf][0], acc[mi][nf][1]);
            *(float2*)(dstp + (size_t)(row + 8) * D_HEAD + col) =
                make_float2(acc[mi][nf][2], acc[mi][nf][3]);
        }
}

// ============================================================
// Kernel 2: RMS norm rows of g_q and g_k (warp per row)
// ============================================================
__global__ __launch_bounds__(256) void rmsnorm_kernel()
{
    const int warp = threadIdx.x >> 5;
    const int lane = threadIdx.x & 31;
    const int row  = blockIdx.x * 8 + warp;
    float* base = (blockIdx.y == 0 ? g_q : g_k) + row * D_HEAD;

    float4 v = *(float4*)(base + lane * 4);
    float ss = v.x * v.x + v.y * v.y + v.z * v.z + v.w * v.w;
    #pragma unroll
    for (int off = 16; off > 0; off >>= 1)
        ss += __shfl_xor_sync(0xffffffffu, ss, off);
    float s = rsqrtf(ss * (1.0f / 128.0f));
    v.x *= s; v.y *= s; v.z *= s; v.w *= s;
    *(float4*)(base + lane * 4) = v;
}

// ============================================================
// Kernel 2b: build pre-split scatter-updated KV cache
// ============================================================
__global__ __launch_bounds__(256) void convert_kv_kernel(
    const float* __restrict__ cK, const float* __restrict__ cV,
    const int* __restrict__ Pp)
{
    const int P = Pp[0];
    int idx = blockIdx.x * 256 + threadIdx.x;      // float4 index over H*L*D
    int e = idx * 4;
    int d = e & 127;
    int l = (e >> 7) & (L_CACHE - 1);
    int h = e >> 19;
    size_t o = (size_t)h * (L_CACHE * D_HEAD) + (size_t)l * D_HEAD + d;
    bool fresh = (l >= P && l < P + M_TOK);
    size_t of = ((size_t)h * M_TOK + (l - P)) * D_HEAD + d;

    float4 kv = fresh ? *(const float4*)(g_k + of) : *(const float4*)(cK + o);
    __nv_bfloat16 a0, b0, a1, b1, a2, b2, a3, b3;
    split_bf16(kv.x, a0, b0); split_bf16(kv.y, a1, b1);
    split_bf16(kv.z, a2, b2); split_bf16(kv.w, a3, b3);
    *(uint2*)(g_kchi + o) = make_uint2(pack2(a0, a1), pack2(a2, a3));
    *(uint2*)(g_kclo + o) = make_uint2(pack2(b0, b1), pack2(b2, b3));

    kv = fresh ? *(const float4*)(g_v + of) : *(const float4*)(cV + o);
    split_bf16(kv.x, a0, b0); split_bf16(kv.y, a1, b1);
    split_bf16(kv.z, a2, b2); split_bf16(kv.w, a3, b3);
    *(uint2*)(g_vchi + o) = make_uint2(pack2(a0, a1), pack2(a2, a3));
    *(uint2*)(g_vclo + o) = make_uint2(pack2(b0, b1), pack2(b2, b3));
}

// ============================================================
// Kernel 3: full-tensor attention, register-P, cp.async double buffer.
// 8 warps = 4(m) x 2(l). Warp: 32m x 32l slice, full d=128.
//   S = Q K^T (mma bf16x3) -> exp in regs -> repack C-frags as A-frags
//   out += P V (mma bf16x3); cross-warp l-reduction once at end.
// grid (4, 16, 2), 256 threads, chunk CL=64.
// ============================================================
#define CL        64
#define QP_B      272                        // 128 bf16 + 8 pad
#define Q_HI_OFF  0
#define Q_LO_OFF  (128 * QP_B)               // 34816
#define BUF0_OFF  (2 * 128 * QP_B)           // 69632
#define KB_KHI    0
#define KB_KLO    (CL * QP_B)                // 17408
#define KB_VHI    (2 * CL * QP_B)            // 34816
#define KB_VLO    (3 * CL * QP_B)            // 52224
#define KVBUF_B   (4 * CL * QP_B)            // 69632
#define DEN_OFF   (BUF0_OFF + 2 * KVBUF_B)   // 208896
#define ATTN_SMEM_B (DEN_OFF + 1024)         // 209920
#define OUT_STAGE BUF0_OFF                   // fp32 stage, pitch 132 floats

__global__ __launch_bounds__(256, 1) void attn_kernel()
{
    extern __shared__ __align__(128) char sm[];
    const uint32_t sb = smem_u32(sm);
    float* denb = (float*)(sm + DEN_OFF);   // [2][128]

    const int t    = threadIdx.x;
    const int lane = t & 31;
    const int wid  = t >> 5;
    const int wm   = wid & 3;     // m-warp: rows wm*32..+32
    const int wl   = wid >> 2;    // l-warp: chunk cols wl*32..+32
    const int lr   = lane & 7;
    const int lg   = lane >> 3;
    const int h    = blockIdx.y;
    const int m0   = blockIdx.x * 128;
    const int z    = blockIdx.z;

    // ---- load Q tile, split to bf16 hi/lo ----
    const float* qbase = g_q + (h * M_TOK + m0) * D_HEAD;
    #pragma unroll
    for (int i = 0; i < 16; ++i) {
        int idx = t + i * 256;         // 0..4095 float4
        int row = idx >> 5;
        int c4  = idx & 31;
        float4 v = *(const float4*)(qbase + row * 128 + c4 * 4);
        __nv_bfloat16 h0, l0, h1, l1, h2, l2, h3, l3;
        split_bf16(v.x, h0, l0); split_bf16(v.y, h1, l1);
        split_bf16(v.z, h2, l2); split_bf16(v.w, h3, l3);
        *(uint2*)(sm + Q_HI_OFF + row * QP_B + c4 * 8) = make_uint2(pack2(h0, h1), pack2(h2, h3));
        *(uint2*)(sm + Q_LO_OFF + row * QP_B + c4 * 8) = make_uint2(pack2(l0, l1), pack2(l2, l3));
    }

    const size_t hoff = (size_t)h * (L_CACHE * D_HEAD);

    // chunk loader: 4 arrays x 64 rows x 256B via cp.async (16B each)
    auto load_chunk = [&](int ch, int buf) {
        const int l0g = z * 2048 + ch * CL;
        const char* srcs[4] = {
            (const char*)(g_kchi + hoff + (size_t)l0g * D_HEAD),
            (const char*)(g_kclo + hoff + (size_t)l0g * D_HEAD),
            (const char*)(g_vchi + hoff + (size_t)l0g * D_HEAD),
            (const char*)(g_vclo + hoff + (size_t)l0g * D_HEAD)
        };
        const uint32_t bo = sb + BUF0_OFF + buf * KVBUF_B;
        #pragma unroll
        for (int i = 0; i < 16; ++i) {
            int idx   = t + i * 256;
            int a     = idx >> 10;
            int local = idx & 1023;
            int row   = local >> 4;
            int c     = local & 15;
            cp_async16(bo + a * (CL * QP_B) + row * QP_B + c * 16,
                       srcs[a] + row * 256 + c * 16);
        }
    };

    // out accumulators: 32m x 128d per warp = 2(mi) x 16(nd) x 4
    float out_acc[2][16][4];
    #pragma unroll
    for (int mi = 0; mi < 2; ++mi)
        #pragma unroll
        for (int nd = 0; nd < 16; ++nd)
            #pragma unroll
            for (int e = 0; e < 4; ++e) out_acc[mi][nd][e] = 0.f;
    float den_acc[2][2] = {{0.f, 0.f}, {0.f, 0.f}};

    load_chunk(0, 0);
    CP_COMMIT();
    CP_WAIT0();
    __syncthreads();

    const int NCH = 2048 / CL;   // 32
    for (int ch = 0; ch < NCH; ++ch) {
        const int buf = ch & 1;
        const uint32_t bo = sb + BUF0_OFF + buf * KVBUF_B;
        if (ch + 1 < NCH) { load_chunk(ch + 1, buf ^ 1); CP_COMMIT(); }

        // ---- S = Q K^T (warp: 32m x its-own 32l) ----
        float s[2][4][4];
        #pragma unroll
        for (int mi = 0; mi < 2; ++mi)
            #pragma unroll
            for (int nj = 0; nj < 4; ++nj)
                #pragma unroll
                for (int e = 0; e < 4; ++e) s[mi][nj][e] = 0.f;

        #pragma unroll
        for (int ks = 0; ks < 8; ++ks) {
            uint32_t aHi[2][4], aLo[2][4], bHi[4][2], bLo[4][2];
            #pragma unroll
            for (int mi = 0; mi < 2; ++mi) {
                int row = wm * 32 + mi * 16 + lr + (lg & 1) * 8;
                uint32_t ad = sb + Q_HI_OFF + row * QP_B + ks * 32 + (lg >> 1) * 16;
                ldm_x4(aHi[mi][0], aHi[mi][1], aHi[mi][2], aHi[mi][3], ad);
                ldm_x4(aLo[mi][0], aLo[mi][1], aLo[mi][2], aLo[mi][3], ad + Q_LO_OFF);
            }
            #pragma unroll
            for (int ng = 0; ng < 2; ++ng) {
                int row = wl * 32 + ng * 16 + (lg >> 1) * 8 + lr;
                uint32_t bd = bo + KB_KHI + row * QP_B + ks * 32 + (lg & 1) * 16;
                uint32_t d0, d1, d2, d3;
                ldm_x4(d0, d1, d2, d3, bd);
                bHi[ng * 2][0] = d0; bHi[ng * 2][1] = d1;
                bHi[ng * 2 + 1][0] = d2; bHi[ng * 2 + 1][1] = d3;
                ldm_x4(d0, d1, d2, d3, bd + (KB_KLO - KB_KHI));
                bLo[ng * 2][0] = d0; bLo[ng * 2][1] = d1;
                bLo[ng * 2 + 1][0] = d2; bLo[ng * 2 + 1][1] = d3;
            }
            #pragma unroll
            for (int mi = 0; mi < 2; ++mi)
                #pragma unroll
                for (int nj = 0; nj < 4; ++nj) {
                    mma16816(s[mi][nj], aHi[mi], bHi[nj]);
                    mma16816(s[mi][nj], aHi[mi], bLo[nj]);
                    mma16816(s[mi][nj], aLo[mi], bHi[nj]);
                }
        }

        // ---- exp + den accumulation (registers only) ----
        #pragma unroll
        for (int mi = 0; mi < 2; ++mi) {
            float sa = 0.f, sbv = 0.f;
            #pragma unroll
            for (int nj = 0; nj < 4; ++nj) {
                s[mi][nj][0] = __expf(s[mi][nj][0]);
                s[mi][nj][1] = __expf(s[mi][nj][1]);
                s[mi][nj][2] = __expf(s[mi][nj][2]);
                s[mi][nj][3] = __expf(s[mi][nj][3]);
                sa  += s[mi][nj][0] + s[mi][nj][1];
                sbv += s[mi][nj][2] + s[mi][nj][3];
            }
            den_acc[mi][0] += sa;
            den_acc[mi][1] += sbv;
        }

        // ---- repack S C-frags into PV A-frags (hi/lo), registers only ----
        // A tile (16m x 16l) kp: regs {c01(nj=2kp), c23(2kp), c01(2kp+1), c23(2kp+1)}
        uint32_t aPhi[2][2][4], aPlo[2][2][4];
        #pragma unroll
        for (int mi = 0; mi < 2; ++mi)
            #pragma unroll
            for (int kp = 0; kp < 2; ++kp)
                #pragma unroll
                for (int half = 0; half < 2; ++half) {
                    const float* sv = s[mi][2 * kp + half];
                    __nv_bfloat16 h0, l0b, h1, l1b;
                    split_bf16(sv[0], h0, l0b); split_bf16(sv[1], h1, l1b);
                    aPhi[mi][kp][half * 2]     = pack2(h0, h1);
                    aPlo[mi][kp][half * 2]     = pack2(l0b, l1b);
                    split_bf16(sv[2], h0, l0b); split_bf16(sv[3], h1, l1b);
                    aPhi[mi][kp][half * 2 + 1] = pack2(h0, h1);
                    aPlo[mi][kp][half * 2 + 1] = pack2(l0b, l1b);
                }

        // ---- out += P V (warp's 32l slice, full 128d) ----
        #pragma unroll
        for (int kp = 0; kp < 2; ++kp) {
            #pragma unroll
            for (int g = 0; g < 8; ++g) {
                int vrow = wl * 32 + kp * 16 + (lg & 1) * 8 + lr;
                int vcol = g * 16 + (lg >> 1) * 8;
                uint32_t bd = bo + KB_VHI + vrow * QP_B + vcol * 2;
                uint32_t d0, d1, d2, d3, e0, e1, e2, e3;
                ldm_x4_t(d0, d1, d2, d3, bd);
                ldm_x4_t(e0, e1, e2, e3, bd + (KB_VLO - KB_VHI));
                uint32_t bh0[2] = {d0, d1}, bh1[2] = {d2, d3};
                uint32_t bl0[2] = {e0, e1}, bl1[2] = {e2, e3};
                #pragma unroll
                for (int mi = 0; mi < 2; ++mi) {
                    mma16816(out_acc[mi][2 * g],     aPhi[mi][kp], bh0);
                    mma16816(out_acc[mi][2 * g],     aPhi[mi][kp], bl0);
                    mma16816(out_acc[mi][2 * g],     aPlo[mi][kp], bh0);
                    mma16816(out_acc[mi][2 * g + 1], aPhi[mi][kp], bh1);
                    mma16816(out_acc[mi][2 * g + 1], aPhi[mi][kp], bl1);
                    mma16816(out_acc[mi][2 * g + 1], aPlo[mi][kp], bh1);
                }
            }
        }

        CP_WAIT0();
        __syncthreads();
    }

    // ---- final denominator reduce ----
    #pragma unroll
    for (int mi = 0; mi < 2; ++mi)
        #pragma unroll
        for (int half = 0; half < 2; ++half) {
            float v = den_acc[mi][half];
            v += __shfl_xor_sync(0xffffffffu, v, 1);
            v += __shfl_xor_sync(0xffffffffu, v, 2);
            if ((lane & 3) == 0)
                denb[wl * 128 + wm * 32 + mi * 16 + half * 8 + (lane >> 2)] = v;
        }

    // ---- cross-warp (wl) reduction of out via smem stage ----
    float* stage = (float*)(sm + OUT_STAGE);   // [128][132]
    if (wl == 0) {
        #pragma unroll
        for (int mi = 0; mi < 2; ++mi)
            #pragma unroll
            for (int nd = 0; nd < 16; ++nd) {
                int row = wm * 32 + mi * 16 + (lane >> 2);
                int col = nd * 8 + (lane & 3) * 2;
                *(float2*)(stage + row * 132 + col) =
                    make_float2(out_acc[mi][nd][0], out_acc[mi][nd][1]);
                *(float2*)(stage + (row + 8) * 132 + col) =
                    make_float2(out_acc[mi][nd][2], out_acc[mi][nd][3]);
            }
    }
    __syncthreads();

    float* po = g_po + ((size_t)(z * H_HEADS + h) * M_TOK + m0) * D_HEAD;
    if (wl == 1) {
        #pragma unroll
        for (int mi = 0; mi < 2; ++mi)
            #pragma unroll
            for (int nd = 0; nd < 16; ++nd) {
                int row = wm * 32 + mi * 16 + (lane >> 2);
                int col = nd * 8 + (lane & 3) * 2;
                float2 a = *(const float2*)(stage + row * 132 + col);
                float2 b = *(const float2*)(stage + (row + 8) * 132 + col);
                *(float2*)(po + (size_t)row * D_HEAD + col) =
                    make_float2(a.x + out_acc[mi][nd][0], a.y + out_acc[mi][nd][1]);
                *(float2*)(po + (size_t)(row + 8) * D_HEAD + col) =
                    make_float2(b.x + out_acc[mi][nd][2], b.y + out_acc[mi][nd][3]);
            }
    }
    if (t < 128)
        g_pd[(z * H_HEADS + h) * M_TOK + m0 + t] = denb[t] + denb[128 + t];
}

// ============================================================
// Kernel 4: combine L-splits and write output [M, H*D]
// ============================================================
__global__ __launch_bounds__(256) void combine_kernel(float* __restrict__ out)
{
    int idx = blockIdx.x * 256 + threadIdx.x;
    int e = idx * 4;
    int d = e & 127;
    int m = (e >> 7) & 511;
    int h = e >> 16;

    float4 a = *(const float4*)(g_po + e);
    float4 b = *(const float4*)(g_po + H_HEADS * M_TOK * D_HEAD + e);
    float dn = g_pd[h * M_TOK + m] + g_pd[H_HEADS * M_TOK + h * M_TOK + m];
    float inv = 1.0f / dn;
    float4 r = make_float4((a.x + b.x) * inv, (a.y + b.y) * inv,
                           (a.z + b.z) * inv, (a.w + b.w) * inv);
    *(float4*)(out + m * N_DIM + h * D_HEAD + d) = r;
}

// ============================================================
extern "C" void kernel_launch(void* const* d_in, const int* in_sizes, int n_in,
                              void* d_out, int out_size)
{
    const float* X  = (const float*)d_in[0];
    const float* W  = (const float*)d_in[1];
    const float* cK = (const float*)d_in[2];
    const float* cV = (const float*)d_in[3];
    const int*   Pp = (const int*)d_in[4];
    float* out = (float*)d_out;

    cudaFuncSetAttribute(attn_kernel,
                         cudaFuncAttributeMaxDynamicSharedMemorySize, ATTN_SMEM_B);
    cudaFuncSetAttribute(qkv_mma_kernel,
                         cudaFuncAttributeMaxDynamicSharedMemorySize, GEMM_SMEM);

    convert_x_kernel<<<(M_TOK * N_DIM / 4) / 256, 256>>>(X);
    convert_w_kernel<<<dim3(N3 / 32, N_DIM / 32), dim3(32, 8)>>>(W);
    qkv_mma_kernel<<<dim3(N3 / 64, M_TOK / 128), 256, GEMM_SMEM>>>();
    rmsnorm_kernel<<<dim3((H_HEADS * M_TOK) / 8, 2), 256>>>();
    convert_kv_kernel<<<(H_HEADS * L_CACHE * D_HEAD / 4) / 256, 256>>>(cK, cV, Pp);
    attn_kernel<<<dim3(M_TOK / 128, H_HEADS, 2), 256, ATTN_SMEM_B>>>();
    combine_kernel<<<(H_HEADS * M_TOK * D_HEAD / 4) / 256, 256>>>(out);
}